// round 11
// baseline (speedup 1.0000x reference)
#include <cuda_runtime.h>
#include <math.h>
#include <stdint.h>

// Problem constants
#define BATCH 4
#define SEQ   1024
#define DIM   1024
#define NH    16
#define DH    64
#define MROWS (BATCH * SEQ)   // 4096

// Scratch buffers (allocation-free rule: __device__ globals)
__device__ float g_Q[MROWS * DIM];
__device__ float g_K[MROWS * DIM];
__device__ float g_V[MROWS * DIM];
__device__ float g_O[MROWS * DIM];

__device__ __forceinline__ uint32_t f32_to_tf32(float f) {
    uint32_t u;
    asm("cvt.rna.tf32.f32 %0, %1;" : "=r"(u) : "f"(f));
    return u;
}

// ----------------------------------------------------------------------------
// Fragment-packed smem layouts for mma.m16n8k8 tf32.
// A tile 128(m) x 16(k):  index(row, col) packs each thread's 4-reg fragment
//   {a0=(r,c) a1=(r+8,c) a2=(r,c+4) a3=(r+8,c+4)} into one 16B-aligned float4.
//   Skew (gcs+gr)&3 spreads banks; verified conflict-free for loads.
// B tile 128(n) x 16(k): packs all 4 n-tiles' 2-reg fragments into 8 words
//   (two LDS.128 per thread per k-step).
// ----------------------------------------------------------------------------
__device__ __forceinline__ int a2_idx(int row, int col) {
    const int wm2 = row >> 6;
    const int r   = row & 63;
    const int mt  = r >> 4;
    const int q   = r & 15;
    const int slotR = q >> 3;
    const int gr  = q & 7;
    const int ks  = col >> 3;
    const int cc  = col & 7;
    const int slotC = cc >> 2;
    const int gcs = cc & 3;
    const int gsk = (gcs + gr) & 3;
    return ((((wm2 * 2 + ks) * 8 + gr) * 4 + gsk) * 20) + mt * 4 + slotR + slotC * 2;
}

__device__ __forceinline__ int b2_idx(int n, int col) {
    const int wn2 = n >> 5;
    const int r   = n & 31;
    const int nt  = r >> 3;
    const int gr  = r & 7;
    const int ks  = col >> 3;
    const int cc  = col & 7;
    const int slotC = cc >> 2;
    const int gcs = cc & 3;
    const int gsk = (gcs + gr) & 3;
    return ((((wn2 * 2 + ks) * 8 + gr) * 4 + gsk) * 12) + nt * 2 + slotC;
}

// ----------------------------------------------------------------------------
// TF32 tensor-core NT GEMM with bias, fused over blockIdx.z (up to 3 problems
// sharing the same A): C[m,n] = sum_k A[m,k]*Wz[n,k] + biasz[n]
// Tile 128x128x16, 8 warps (warp tile 64x32 = 4x4 mma), fragment-packed smem.
// ----------------------------------------------------------------------------
__global__ __launch_bounds__(256, 2) void gemm3_tf32_nt_bias(
    const float* __restrict__ A,
    const float* __restrict__ W0, const float* __restrict__ W1, const float* __restrict__ W2,
    const float* __restrict__ b0, const float* __restrict__ b1, const float* __restrict__ b2,
    float* __restrict__ C0, float* __restrict__ C1, float* __restrict__ C2,
    int M, int N, int K)
{
    const int z = blockIdx.z;
    const float* B    = (z == 0) ? W0 : (z == 1) ? W1 : W2;
    const float* bias = (z == 0) ? b0 : (z == 1) ? b1 : b2;
    float* C          = (z == 0) ? C0 : (z == 1) ? C1 : C2;

    __shared__ __align__(16) uint32_t As2[2560];
    __shared__ __align__(16) uint32_t Bs2[3072];

    const int bm   = blockIdx.y * 128;
    const int bn   = blockIdx.x * 128;
    const int t    = threadIdx.x;
    const int warp = t >> 5;
    const int lane = t & 31;
    const int wm2  = warp & 1;           // m half 0/1
    const int wn2  = warp >> 1;          // n quarter 0..3
    const int gr   = lane >> 2;
    const int gcs  = lane & 3;
    const int gsk  = (gcs + gr) & 3;

    // Gmem loader mapping: thread covers row (t>>1), k-cols (t&1)*8 .. +7
    const int lrow = t >> 1;
    const int lk   = (t & 1) * 8;
    const float* Ap = A + (size_t)(bm + lrow) * K + lk;
    const float* Bp = B + (size_t)(bn + lrow) * K + lk;

    float acc[4][4][4];
#pragma unroll
    for (int mt = 0; mt < 4; mt++)
#pragma unroll
        for (int nt = 0; nt < 4; nt++)
#pragma unroll
            for (int c = 0; c < 4; c++) acc[mt][nt][c] = 0.0f;

    float4 ra0 = *(const float4*)(Ap);
    float4 ra1 = *(const float4*)(Ap + 4);
    float4 rb0 = *(const float4*)(Bp);
    float4 rb1 = *(const float4*)(Bp + 4);

    for (int k0 = 0; k0 < K; k0 += 16) {
        // Stage current tile into fragment-packed layout
        {
            float av[8] = {ra0.x, ra0.y, ra0.z, ra0.w, ra1.x, ra1.y, ra1.z, ra1.w};
            float bv[8] = {rb0.x, rb0.y, rb0.z, rb0.w, rb1.x, rb1.y, rb1.z, rb1.w};
#pragma unroll
            for (int i = 0; i < 8; i++) {
                As2[a2_idx(lrow, lk + i)] = f32_to_tf32(av[i]);
                Bs2[b2_idx(lrow, lk + i)] = f32_to_tf32(bv[i]);
            }
        }
        __syncthreads();

        if (k0 + 16 < K) {
            ra0 = *(const float4*)(Ap + k0 + 16);
            ra1 = *(const float4*)(Ap + k0 + 20);
            rb0 = *(const float4*)(Bp + k0 + 16);
            rb1 = *(const float4*)(Bp + k0 + 20);
        }

#pragma unroll
        for (int ks = 0; ks < 2; ks++) {
            const uint32_t* abase = &As2[(((wm2 * 2 + ks) * 8 + gr) * 4 + gsk) * 20];
            const uint32_t* bbase = &Bs2[(((wn2 * 2 + ks) * 8 + gr) * 4 + gsk) * 12];

            uint4 af[4];
#pragma unroll
            for (int mt = 0; mt < 4; mt++)
                af[mt] = *(const uint4*)(abase + mt * 4);
            const uint4 b01 = *(const uint4*)(bbase);       // nt0:{c0,c4}, nt1:{c0,c4}
            const uint4 b23 = *(const uint4*)(bbase + 4);   // nt2, nt3
            const uint32_t bf[4][2] = {{b01.x, b01.y}, {b01.z, b01.w},
                                       {b23.x, b23.y}, {b23.z, b23.w}};
#pragma unroll
            for (int mt = 0; mt < 4; mt++)
#pragma unroll
                for (int nt = 0; nt < 4; nt++) {
                    asm volatile(
                        "mma.sync.aligned.m16n8k8.row.col.f32.tf32.tf32.f32 "
                        "{%0,%1,%2,%3}, {%4,%5,%6,%7}, {%8,%9}, {%0,%1,%2,%3};"
                        : "+f"(acc[mt][nt][0]), "+f"(acc[mt][nt][1]),
                          "+f"(acc[mt][nt][2]), "+f"(acc[mt][nt][3])
                        : "r"(af[mt].x), "r"(af[mt].y), "r"(af[mt].z), "r"(af[mt].w),
                          "r"(bf[nt][0]), "r"(bf[nt][1]));
                }
        }
        __syncthreads();
    }

    // Epilogue: bias add + store (c0,c1 at row; c2,c3 at row+8)
    const int wm = wm2 * 64;
    const int wn = wn2 * 32;
#pragma unroll
    for (int mt = 0; mt < 4; mt++) {
        const int m0 = bm + wm + mt * 16 + gr;
#pragma unroll
        for (int nt = 0; nt < 4; nt++) {
            const int n0 = bn + wn + nt * 8 + gcs * 2;
            const float bv0 = bias[n0];
            const float bv1 = bias[n0 + 1];
            float2 v01;
            v01.x = acc[mt][nt][0] + bv0;
            v01.y = acc[mt][nt][1] + bv1;
            *(float2*)&C[(size_t)m0 * N + n0] = v01;
            float2 v23;
            v23.x = acc[mt][nt][2] + bv0;
            v23.y = acc[mt][nt][3] + bv1;
            *(float2*)&C[(size_t)(m0 + 8) * N + n0] = v23;
        }
    }
}

// ----------------------------------------------------------------------------
// RoPE, REVERSE rotation (-sin), half-split pairs (j, j+32). One launch does
// both Q (blockIdx.y=0) and K (blockIdx.y=1).
// ----------------------------------------------------------------------------
__global__ void rope_negsin_qk(float* __restrict__ Q, float* __restrict__ K)
{
    float* X = blockIdx.y ? K : Q;
    const int idx = blockIdx.x * blockDim.x + threadIdx.x;
    const int total = BATCH * SEQ * NH * 32;
    if (idx >= total) return;
    const int j    = idx & 31;
    const int rest = idx >> 5;            // ((b*SEQ + s)*NH + h)
    const int s    = (rest / NH) % SEQ;
    const size_t base = (size_t)rest * DH;

    const float inv_freq = expf(-((float)(2 * j) / (float)DH) * logf(10000.0f));
    const float ang = (float)s * inv_freq;
    float c, sn;
    sincosf(ang, &c, &sn);

    const float x1 = X[base + j];
    const float x2 = X[base + j + 32];
    X[base + j]      = x1 * c + x2 * sn;   // reverse rotation
    X[base + j + 32] = x2 * c - x1 * sn;
}

// ----------------------------------------------------------------------------
// Flash attention (fp32 SIMT): per (b, h, 64-row q-tile), 32-key tiles,
// static smem 44.5KB. Unchanged (known-good).
// ----------------------------------------------------------------------------
__global__ __launch_bounds__(256) void flash_attn(
    const float* __restrict__ Q, const float* __restrict__ K,
    const float* __restrict__ V, float* __restrict__ O)
{
    __shared__ float Qt[64][68];
    __shared__ float Kt[64][36];
    __shared__ float Vs[32][68];
    __shared__ float Pq[64][36];

    const int qt = blockIdx.x;
    const int h  = blockIdx.y;
    const int b  = blockIdx.z;
    const int t  = threadIdx.x;
    const int tx = t & 15;
    const int ty = t >> 4;

    const int base_col = h * DH;
    const int q0 = qt * 64;
    const float scale = 0.125f;

    for (int u = t; u < 64 * 16; u += 256) {
        const int row = u >> 4;
        const int c   = (u & 15) * 4;
        const float4 v = *(const float4*)&Q[((size_t)(b * SEQ + q0 + row)) * DIM + base_col + c];
        Qt[c + 0][row] = v.x * scale;
        Qt[c + 1][row] = v.y * scale;
        Qt[c + 2][row] = v.z * scale;
        Qt[c + 3][row] = v.w * scale;
    }

    float m_i[4], l_i[4], acc[4][4];
#pragma unroll
    for (int i = 0; i < 4; i++) {
        m_i[i] = -1e30f;
        l_i[i] = 0.0f;
#pragma unroll
        for (int j = 0; j < 4; j++) acc[i][j] = 0.0f;
    }

    for (int kt = 0; kt < SEQ; kt += 32) {
        __syncthreads();
        for (int u = t; u < 32 * 16; u += 256) {
            const int row = u >> 4;
            const int c   = (u & 15) * 4;
            const size_t g = ((size_t)(b * SEQ + kt + row)) * DIM + base_col + c;
            const float4 kv = *(const float4*)&K[g];
            Kt[c + 0][row] = kv.x;
            Kt[c + 1][row] = kv.y;
            Kt[c + 2][row] = kv.z;
            Kt[c + 3][row] = kv.w;
            *(float4*)&Vs[row][c] = *(const float4*)&V[g];
        }
        __syncthreads();

        float s00 = 0.f, s01 = 0.f, s10 = 0.f, s11 = 0.f;
        float s20 = 0.f, s21 = 0.f, s30 = 0.f, s31 = 0.f;
#pragma unroll 16
        for (int d = 0; d < 64; d++) {
            const float4 qa = *(const float4*)&Qt[d][ty * 4];
            const float2 kb = *(const float2*)&Kt[d][tx * 2];
            s00 = fmaf(qa.x, kb.x, s00); s01 = fmaf(qa.x, kb.y, s01);
            s10 = fmaf(qa.y, kb.x, s10); s11 = fmaf(qa.y, kb.y, s11);
            s20 = fmaf(qa.z, kb.x, s20); s21 = fmaf(qa.z, kb.y, s21);
            s30 = fmaf(qa.w, kb.x, s30); s31 = fmaf(qa.w, kb.y, s31);
        }
        float sv[4][2] = {{s00, s01}, {s10, s11}, {s20, s21}, {s30, s31}};

#pragma unroll
        for (int i = 0; i < 4; i++) {
            float mx = fmaxf(sv[i][0], sv[i][1]);
#pragma unroll
            for (int o = 1; o < 16; o <<= 1)
                mx = fmaxf(mx, __shfl_xor_sync(0xffffffffu, mx, o));
            const float mn = fmaxf(m_i[i], mx);
            const float corr = __expf(m_i[i] - mn);
            m_i[i] = mn;
            const float p0 = __expf(sv[i][0] - mn);
            const float p1 = __expf(sv[i][1] - mn);
            float ps = p0 + p1;
#pragma unroll
            for (int o = 1; o < 16; o <<= 1)
                ps += __shfl_xor_sync(0xffffffffu, ps, o);
            l_i[i] = l_i[i] * corr + ps;
#pragma unroll
            for (int j = 0; j < 4; j++) acc[i][j] *= corr;
            sv[i][0] = p0;
            sv[i][1] = p1;
        }

#pragma unroll
        for (int i = 0; i < 4; i++) {
            float2 p2;
            p2.x = sv[i][0];
            p2.y = sv[i][1];
            *(float2*)&Pq[ty * 4 + i][tx * 2] = p2;
        }
        __syncthreads();

#pragma unroll 8
        for (int k = 0; k < 32; k++) {
            const float a0 = Pq[ty * 4 + 0][k];
            const float a1 = Pq[ty * 4 + 1][k];
            const float a2 = Pq[ty * 4 + 2][k];
            const float a3 = Pq[ty * 4 + 3][k];
            const float4 v4 = *(const float4*)&Vs[k][tx * 4];
            acc[0][0] = fmaf(a0, v4.x, acc[0][0]);
            acc[0][1] = fmaf(a0, v4.y, acc[0][1]);
            acc[0][2] = fmaf(a0, v4.z, acc[0][2]);
            acc[0][3] = fmaf(a0, v4.w, acc[0][3]);
            acc[1][0] = fmaf(a1, v4.x, acc[1][0]);
            acc[1][1] = fmaf(a1, v4.y, acc[1][1]);
            acc[1][2] = fmaf(a1, v4.z, acc[1][2]);
            acc[1][3] = fmaf(a1, v4.w, acc[1][3]);
            acc[2][0] = fmaf(a2, v4.x, acc[2][0]);
            acc[2][1] = fmaf(a2, v4.y, acc[2][1]);
            acc[2][2] = fmaf(a2, v4.z, acc[2][2]);
            acc[2][3] = fmaf(a2, v4.w, acc[2][3]);
            acc[3][0] = fmaf(a3, v4.x, acc[3][0]);
            acc[3][1] = fmaf(a3, v4.y, acc[3][1]);
            acc[3][2] = fmaf(a3, v4.z, acc[3][2]);
            acc[3][3] = fmaf(a3, v4.w, acc[3][3]);
        }
    }

#pragma unroll
    for (int i = 0; i < 4; i++) {
        const float inv = 1.0f / l_i[i];
        float4 o;
        o.x = acc[i][0] * inv;
        o.y = acc[i][1] * inv;
        o.z = acc[i][2] * inv;
        o.w = acc[i][3] * inv;
        *(float4*)&O[((size_t)(b * SEQ + q0 + ty * 4 + i)) * DIM + base_col + tx * 4] = o;
    }
}

// ----------------------------------------------------------------------------
// Launch — strict dict-order input mapping: x, Wq, bq, Wk, bk, Wv, bv, Wo, bo
// ----------------------------------------------------------------------------
extern "C" void kernel_launch(void* const* d_in, const int* in_sizes, int n_in,
                              void* d_out, int out_size)
{
    (void)in_sizes; (void)n_in; (void)out_size;
    const float* x  = (const float*)d_in[0];
    const float* Wq = (const float*)d_in[1];
    const float* bq = (const float*)d_in[2];
    const float* Wk = (const float*)d_in[3];
    const float* bk = (const float*)d_in[4];
    const float* Wv = (const float*)d_in[5];
    const float* bv = (const float*)d_in[6];
    const float* Wo = (const float*)d_in[7];
    const float* bo = (const float*)d_in[8];
    float* out = (float*)d_out;

    float *Q, *K, *V, *O;
    cudaGetSymbolAddress((void**)&Q, g_Q);
    cudaGetSymbolAddress((void**)&K, g_K);
    cudaGetSymbolAddress((void**)&V, g_V);
    cudaGetSymbolAddress((void**)&O, g_O);

    // Fused Q/K/V projections: one launch, z selects the problem
    const dim3 g3(DIM / 128, MROWS / 128, 3);   // (8, 32, 3)
    gemm3_tf32_nt_bias<<<g3, 256>>>(x, Wq, Wk, Wv, bq, bk, bv, Q, K, V,
                                    MROWS, DIM, DIM);

    // RoPE on Q and K in one launch
    const int rope_threads = BATCH * SEQ * NH * 32;
    const dim3 rgrid((rope_threads + 255) / 256, 2);
    rope_negsin_qk<<<rgrid, 256>>>(Q, K);

    const dim3 agrid(SEQ / 64, NH, BATCH);      // (16, 16, 4)
    flash_attn<<<agrid, 256>>>(Q, K, V, O);

    // Output projection (single problem via same kernel, z-dim 1)
    const dim3 g1(DIM / 128, MROWS / 128, 1);
    gemm3_tf32_nt_bias<<<g1, 256>>>(O, Wo, Wo, Wo, bo, bo, bo, out, out, out,
                                    MROWS, DIM, DIM);
}

// round 12
// speedup vs baseline: 1.2519x; 1.2519x over previous
#include <cuda_runtime.h>
#include <cuda_fp16.h>
#include <math.h>
#include <stdint.h>

// Problem constants
#define BATCH 4
#define SEQ   1024
#define DIM   1024
#define NH    16
#define DH    64
#define MROWS (BATCH * SEQ)   // 4096

// Scratch buffers (allocation-free rule: __device__ globals)
__device__ float g_Q[MROWS * DIM];
__device__ float g_K[MROWS * DIM];
__device__ float g_V[MROWS * DIM];
__device__ float g_O[MROWS * DIM];

// ----------------------------------------------------------------------------
// FP16 tensor-core NT GEMM with bias, fused over blockIdx.z (up to 3 problems
// sharing A): C[m,n] = sum_k A[m,k]*Wz[n,k] + biasz[n]
// mma.sync.m16n8k16.row.col.f32.f16.f16.f32, fragments via ldmatrix.x4.
// Tile 128x128x16, 8 warps (warp tile 64m x 32n = 4x4 mma tiles).
// Smem: halves, row stride 24 (48B) -> conflict-free ldmatrix phases.
// ----------------------------------------------------------------------------
#define SAST 24   // smem row stride in halves

__global__ __launch_bounds__(256, 2) void gemm3_f16_nt_bias(
    const float* __restrict__ A,
    const float* __restrict__ W0, const float* __restrict__ W1, const float* __restrict__ W2,
    const float* __restrict__ b0, const float* __restrict__ b1, const float* __restrict__ b2,
    float* __restrict__ C0, float* __restrict__ C1, float* __restrict__ C2,
    int M, int N, int K)
{
    const int z = blockIdx.z;
    const float* B    = (z == 0) ? W0 : (z == 1) ? W1 : W2;
    const float* bias = (z == 0) ? b0 : (z == 1) ? b1 : b2;
    float* C          = (z == 0) ? C0 : (z == 1) ? C1 : C2;

    __shared__ __align__(16) __half As[128 * SAST];
    __shared__ __align__(16) __half Bs[128 * SAST];

    const int bm   = blockIdx.y * 128;
    const int bn   = blockIdx.x * 128;
    const int t    = threadIdx.x;
    const int warp = t >> 5;
    const int lane = t & 31;
    const int wm2  = warp & 1;           // m half: 0/1 (x64)
    const int wn2  = warp >> 1;          // n quarter: 0..3 (x32)

    // Gmem loader mapping: row (t>>1), k-cols (t&1)*8 .. +7
    const int lrow = t >> 1;
    const int lk   = (t & 1) * 8;
    const float* Ap = A + (size_t)(bm + lrow) * K + lk;
    const float* Bp = B + (size_t)(bn + lrow) * K + lk;
    __half* AsW = &As[lrow * SAST + lk];
    __half* BsW = &Bs[lrow * SAST + lk];

    // ldmatrix source addresses (byte offsets into As/Bs), fixed per thread:
    // A (per mt): matrices {a0:r+0,c0 | a1:r+8,c0 | a2:r+0,c8 | a3:r+8,c8}
    const int sub = lane >> 3;          // 0..3 = matrix id
    const int lr  = lane & 7;
    const int a_row_base = wm2 * 64 + ((sub & 1) * 8) + lr;
    const int a_col      = (sub >> 1) * 8;
    // B (per pair g): matrices {b0:n+0,c0 | b1:n+0,c8 | b0':n+8,c0 | b1':n+8,c8}
    const int b_row_base = wn2 * 32 + ((sub >> 1) * 8) + lr;
    const int b_col      = (sub & 1) * 8;

    uint32_t a_addr[4], b_addr[2];
    {
        uint32_t as_base, bs_base;
        asm("{ .reg .u64 tmp; cvta.to.shared.u64 tmp, %1; cvt.u32.u64 %0, tmp; }"
            : "=r"(as_base) : "l"(As));
        asm("{ .reg .u64 tmp; cvta.to.shared.u64 tmp, %1; cvt.u32.u64 %0, tmp; }"
            : "=r"(bs_base) : "l"(Bs));
#pragma unroll
        for (int mt = 0; mt < 4; mt++)
            a_addr[mt] = as_base + 2 * ((a_row_base + mt * 16) * SAST + a_col);
#pragma unroll
        for (int g = 0; g < 2; g++)
            b_addr[g] = bs_base + 2 * ((b_row_base + g * 16) * SAST + b_col);
    }

    float acc[4][4][4];
#pragma unroll
    for (int mt = 0; mt < 4; mt++)
#pragma unroll
        for (int nt = 0; nt < 4; nt++)
#pragma unroll
            for (int c = 0; c < 4; c++) acc[mt][nt][c] = 0.0f;

    // Prefetch first k-tile
    float4 ra0 = *(const float4*)(Ap);
    float4 ra1 = *(const float4*)(Ap + 4);
    float4 rb0 = *(const float4*)(Bp);
    float4 rb1 = *(const float4*)(Bp + 4);

    for (int k0 = 0; k0 < K; k0 += 16) {
        // Convert to fp16 and stage (one STS.128 per matrix per thread)
        {
            uint4 av, bv;
            ((__half2*)&av)[0] = __floats2half2_rn(ra0.x, ra0.y);
            ((__half2*)&av)[1] = __floats2half2_rn(ra0.z, ra0.w);
            ((__half2*)&av)[2] = __floats2half2_rn(ra1.x, ra1.y);
            ((__half2*)&av)[3] = __floats2half2_rn(ra1.z, ra1.w);
            ((__half2*)&bv)[0] = __floats2half2_rn(rb0.x, rb0.y);
            ((__half2*)&bv)[1] = __floats2half2_rn(rb0.z, rb0.w);
            ((__half2*)&bv)[2] = __floats2half2_rn(rb1.x, rb1.y);
            ((__half2*)&bv)[3] = __floats2half2_rn(rb1.z, rb1.w);
            *(uint4*)AsW = av;
            *(uint4*)BsW = bv;
        }
        __syncthreads();

        // Prefetch next tile
        if (k0 + 16 < K) {
            ra0 = *(const float4*)(Ap + k0 + 16);
            ra1 = *(const float4*)(Ap + k0 + 20);
            rb0 = *(const float4*)(Bp + k0 + 16);
            rb1 = *(const float4*)(Bp + k0 + 24 - 4);
            rb1 = *(const float4*)(Bp + k0 + 20);
        }

        // Load fragments via ldmatrix
        uint32_t af[4][4];
#pragma unroll
        for (int mt = 0; mt < 4; mt++) {
            asm volatile(
                "ldmatrix.sync.aligned.m8n8.x4.shared.b16 {%0,%1,%2,%3}, [%4];"
                : "=r"(af[mt][0]), "=r"(af[mt][1]), "=r"(af[mt][2]), "=r"(af[mt][3])
                : "r"(a_addr[mt]));
        }
        uint32_t bf[4][2];
#pragma unroll
        for (int g = 0; g < 2; g++) {
            asm volatile(
                "ldmatrix.sync.aligned.m8n8.x4.shared.b16 {%0,%1,%2,%3}, [%4];"
                : "=r"(bf[g * 2][0]), "=r"(bf[g * 2][1]),
                  "=r"(bf[g * 2 + 1][0]), "=r"(bf[g * 2 + 1][1])
                : "r"(b_addr[g]));
        }

#pragma unroll
        for (int mt = 0; mt < 4; mt++)
#pragma unroll
            for (int nt = 0; nt < 4; nt++) {
                asm volatile(
                    "mma.sync.aligned.m16n8k16.row.col.f32.f16.f16.f32 "
                    "{%0,%1,%2,%3}, {%4,%5,%6,%7}, {%8,%9}, {%0,%1,%2,%3};"
                    : "+f"(acc[mt][nt][0]), "+f"(acc[mt][nt][1]),
                      "+f"(acc[mt][nt][2]), "+f"(acc[mt][nt][3])
                    : "r"(af[mt][0]), "r"(af[mt][1]), "r"(af[mt][2]), "r"(af[mt][3]),
                      "r"(bf[nt][0]), "r"(bf[nt][1]));
            }
        __syncthreads();
    }

    // Epilogue: bias add + store (c0,c1 at row gr; c2,c3 at gr+8)
    const int gr  = lane >> 2;
    const int gcs = lane & 3;
#pragma unroll
    for (int mt = 0; mt < 4; mt++) {
        const int m0 = bm + wm2 * 64 + mt * 16 + gr;
#pragma unroll
        for (int nt = 0; nt < 4; nt++) {
            const int n0 = bn + wn2 * 32 + nt * 8 + gcs * 2;
            const float bv0 = bias[n0];
            const float bv1 = bias[n0 + 1];
            float2 v01;
            v01.x = acc[mt][nt][0] + bv0;
            v01.y = acc[mt][nt][1] + bv1;
            *(float2*)&C[(size_t)m0 * N + n0] = v01;
            float2 v23;
            v23.x = acc[mt][nt][2] + bv0;
            v23.y = acc[mt][nt][3] + bv1;
            *(float2*)&C[(size_t)(m0 + 8) * N + n0] = v23;
        }
    }
}

// ----------------------------------------------------------------------------
// RoPE, REVERSE rotation (-sin), half-split pairs (j, j+32); Q and K in one
// launch via blockIdx.y.
// ----------------------------------------------------------------------------
__global__ void rope_negsin_qk(float* __restrict__ Q, float* __restrict__ K)
{
    float* X = blockIdx.y ? K : Q;
    const int idx = blockIdx.x * blockDim.x + threadIdx.x;
    const int total = BATCH * SEQ * NH * 32;
    if (idx >= total) return;
    const int j    = idx & 31;
    const int rest = idx >> 5;            // ((b*SEQ + s)*NH + h)
    const int s    = (rest / NH) % SEQ;
    const size_t base = (size_t)rest * DH;

    const float inv_freq = expf(-((float)(2 * j) / (float)DH) * logf(10000.0f));
    const float ang = (float)s * inv_freq;
    float c, sn;
    sincosf(ang, &c, &sn);

    const float x1 = X[base + j];
    const float x2 = X[base + j + 32];
    X[base + j]      = x1 * c + x2 * sn;   // reverse rotation
    X[base + j + 32] = x2 * c - x1 * sn;
}

// ----------------------------------------------------------------------------
// Flash attention (fp32 SIMT): per (b, h, 64-row q-tile), 32-key tiles,
// static smem 44.5KB. Unchanged (known-good).
// ----------------------------------------------------------------------------
__global__ __launch_bounds__(256) void flash_attn(
    const float* __restrict__ Q, const float* __restrict__ K,
    const float* __restrict__ V, float* __restrict__ O)
{
    __shared__ float Qt[64][68];
    __shared__ float Kt[64][36];
    __shared__ float Vs[32][68];
    __shared__ float Pq[64][36];

    const int qt = blockIdx.x;
    const int h  = blockIdx.y;
    const int b  = blockIdx.z;
    const int t  = threadIdx.x;
    const int tx = t & 15;
    const int ty = t >> 4;

    const int base_col = h * DH;
    const int q0 = qt * 64;
    const float scale = 0.125f;

    for (int u = t; u < 64 * 16; u += 256) {
        const int row = u >> 4;
        const int c   = (u & 15) * 4;
        const float4 v = *(const float4*)&Q[((size_t)(b * SEQ + q0 + row)) * DIM + base_col + c];
        Qt[c + 0][row] = v.x * scale;
        Qt[c + 1][row] = v.y * scale;
        Qt[c + 2][row] = v.z * scale;
        Qt[c + 3][row] = v.w * scale;
    }

    float m_i[4], l_i[4], acc[4][4];
#pragma unroll
    for (int i = 0; i < 4; i++) {
        m_i[i] = -1e30f;
        l_i[i] = 0.0f;
#pragma unroll
        for (int j = 0; j < 4; j++) acc[i][j] = 0.0f;
    }

    for (int kt = 0; kt < SEQ; kt += 32) {
        __syncthreads();
        for (int u = t; u < 32 * 16; u += 256) {
            const int row = u >> 4;
            const int c   = (u & 15) * 4;
            const size_t g = ((size_t)(b * SEQ + kt + row)) * DIM + base_col + c;
            const float4 kv = *(const float4*)&K[g];
            Kt[c + 0][row] = kv.x;
            Kt[c + 1][row] = kv.y;
            Kt[c + 2][row] = kv.z;
            Kt[c + 3][row] = kv.w;
            *(float4*)&Vs[row][c] = *(const float4*)&V[g];
        }
        __syncthreads();

        float s00 = 0.f, s01 = 0.f, s10 = 0.f, s11 = 0.f;
        float s20 = 0.f, s21 = 0.f, s30 = 0.f, s31 = 0.f;
#pragma unroll 16
        for (int d = 0; d < 64; d++) {
            const float4 qa = *(const float4*)&Qt[d][ty * 4];
            const float2 kb = *(const float2*)&Kt[d][tx * 2];
            s00 = fmaf(qa.x, kb.x, s00); s01 = fmaf(qa.x, kb.y, s01);
            s10 = fmaf(qa.y, kb.x, s10); s11 = fmaf(qa.y, kb.y, s11);
            s20 = fmaf(qa.z, kb.x, s20); s21 = fmaf(qa.z, kb.y, s21);
            s30 = fmaf(qa.w, kb.x, s30); s31 = fmaf(qa.w, kb.y, s31);
        }
        float sv[4][2] = {{s00, s01}, {s10, s11}, {s20, s21}, {s30, s31}};

#pragma unroll
        for (int i = 0; i < 4; i++) {
            float mx = fmaxf(sv[i][0], sv[i][1]);
#pragma unroll
            for (int o = 1; o < 16; o <<= 1)
                mx = fmaxf(mx, __shfl_xor_sync(0xffffffffu, mx, o));
            const float mn = fmaxf(m_i[i], mx);
            const float corr = __expf(m_i[i] - mn);
            m_i[i] = mn;
            const float p0 = __expf(sv[i][0] - mn);
            const float p1 = __expf(sv[i][1] - mn);
            float ps = p0 + p1;
#pragma unroll
            for (int o = 1; o < 16; o <<= 1)
                ps += __shfl_xor_sync(0xffffffffu, ps, o);
            l_i[i] = l_i[i] * corr + ps;
#pragma unroll
            for (int j = 0; j < 4; j++) acc[i][j] *= corr;
            sv[i][0] = p0;
            sv[i][1] = p1;
        }

#pragma unroll
        for (int i = 0; i < 4; i++) {
            float2 p2;
            p2.x = sv[i][0];
            p2.y = sv[i][1];
            *(float2*)&Pq[ty * 4 + i][tx * 2] = p2;
        }
        __syncthreads();

#pragma unroll 8
        for (int k = 0; k < 32; k++) {
            const float a0 = Pq[ty * 4 + 0][k];
            const float a1 = Pq[ty * 4 + 1][k];
            const float a2 = Pq[ty * 4 + 2][k];
            const float a3 = Pq[ty * 4 + 3][k];
            const float4 v4 = *(const float4*)&Vs[k][tx * 4];
            acc[0][0] = fmaf(a0, v4.x, acc[0][0]);
            acc[0][1] = fmaf(a0, v4.y, acc[0][1]);
            acc[0][2] = fmaf(a0, v4.z, acc[0][2]);
            acc[0][3] = fmaf(a0, v4.w, acc[0][3]);
            acc[1][0] = fmaf(a1, v4.x, acc[1][0]);
            acc[1][1] = fmaf(a1, v4.y, acc[1][1]);
            acc[1][2] = fmaf(a1, v4.z, acc[1][2]);
            acc[1][3] = fmaf(a1, v4.w, acc[1][3]);
            acc[2][0] = fmaf(a2, v4.x, acc[2][0]);
            acc[2][1] = fmaf(a2, v4.y, acc[2][1]);
            acc[2][2] = fmaf(a2, v4.z, acc[2][2]);
            acc[2][3] = fmaf(a2, v4.w, acc[2][3]);
            acc[3][0] = fmaf(a3, v4.x, acc[3][0]);
            acc[3][1] = fmaf(a3, v4.y, acc[3][1]);
            acc[3][2] = fmaf(a3, v4.z, acc[3][2]);
            acc[3][3] = fmaf(a3, v4.w, acc[3][3]);
        }
    }

#pragma unroll
    for (int i = 0; i < 4; i++) {
        const float inv = 1.0f / l_i[i];
        float4 o;
        o.x = acc[i][0] * inv;
        o.y = acc[i][1] * inv;
        o.z = acc[i][2] * inv;
        o.w = acc[i][3] * inv;
        *(float4*)&O[((size_t)(b * SEQ + q0 + ty * 4 + i)) * DIM + base_col + tx * 4] = o;
    }
}

// ----------------------------------------------------------------------------
// Launch — strict dict-order input mapping: x, Wq, bq, Wk, bk, Wv, bv, Wo, bo
// ----------------------------------------------------------------------------
extern "C" void kernel_launch(void* const* d_in, const int* in_sizes, int n_in,
                              void* d_out, int out_size)
{
    (void)in_sizes; (void)n_in; (void)out_size;
    const float* x  = (const float*)d_in[0];
    const float* Wq = (const float*)d_in[1];
    const float* bq = (const float*)d_in[2];
    const float* Wk = (const float*)d_in[3];
    const float* bk = (const float*)d_in[4];
    const float* Wv = (const float*)d_in[5];
    const float* bv = (const float*)d_in[6];
    const float* Wo = (const float*)d_in[7];
    const float* bo = (const float*)d_in[8];
    float* out = (float*)d_out;

    float *Q, *K, *V, *O;
    cudaGetSymbolAddress((void**)&Q, g_Q);
    cudaGetSymbolAddress((void**)&K, g_K);
    cudaGetSymbolAddress((void**)&V, g_V);
    cudaGetSymbolAddress((void**)&O, g_O);

    // Fused Q/K/V projections
    const dim3 g3(DIM / 128, MROWS / 128, 3);   // (8, 32, 3)
    gemm3_f16_nt_bias<<<g3, 256>>>(x, Wq, Wk, Wv, bq, bk, bv, Q, K, V,
                                   MROWS, DIM, DIM);

    // RoPE on Q and K in one launch
    const int rope_threads = BATCH * SEQ * NH * 32;
    const dim3 rgrid((rope_threads + 255) / 256, 2);
    rope_negsin_qk<<<rgrid, 256>>>(Q, K);

    const dim3 agrid(SEQ / 64, NH, BATCH);      // (16, 16, 4)
    flash_attn<<<agrid, 256>>>(Q, K, V, O);

    // Output projection
    const dim3 g1(DIM / 128, MROWS / 128, 1);
    gemm3_f16_nt_bias<<<g1, 256>>>(O, Wo, Wo, Wo, bo, bo, bo, out, out, out,
                                   MROWS, DIM, DIM);
}

// round 13
// speedup vs baseline: 2.8052x; 2.2408x over previous
#include <cuda_runtime.h>
#include <cuda_fp16.h>
#include <math.h>
#include <stdint.h>

// Problem constants
#define BATCH 4
#define SEQ   1024
#define DIM   1024
#define NH    16
#define DH    64
#define MROWS (BATCH * SEQ)   // 4096

// Scratch buffers (allocation-free rule: __device__ globals)
__device__ float g_Q[MROWS * DIM];
__device__ float g_K[MROWS * DIM];
__device__ float g_V[MROWS * DIM];
__device__ float g_O[MROWS * DIM];

// ----------------------------------------------------------------------------
// FP16 tensor-core NT GEMM with bias, fused over blockIdx.z (unchanged, R12).
// ----------------------------------------------------------------------------
#define SAST 24   // smem row stride in halves

__global__ __launch_bounds__(256, 2) void gemm3_f16_nt_bias(
    const float* __restrict__ A,
    const float* __restrict__ W0, const float* __restrict__ W1, const float* __restrict__ W2,
    const float* __restrict__ b0, const float* __restrict__ b1, const float* __restrict__ b2,
    float* __restrict__ C0, float* __restrict__ C1, float* __restrict__ C2,
    int M, int N, int K)
{
    const int z = blockIdx.z;
    const float* B    = (z == 0) ? W0 : (z == 1) ? W1 : W2;
    const float* bias = (z == 0) ? b0 : (z == 1) ? b1 : b2;
    float* C          = (z == 0) ? C0 : (z == 1) ? C1 : C2;

    __shared__ __align__(16) __half As[128 * SAST];
    __shared__ __align__(16) __half Bs[128 * SAST];

    const int bm   = blockIdx.y * 128;
    const int bn   = blockIdx.x * 128;
    const int t    = threadIdx.x;
    const int warp = t >> 5;
    const int lane = t & 31;
    const int wm2  = warp & 1;
    const int wn2  = warp >> 1;

    const int lrow = t >> 1;
    const int lk   = (t & 1) * 8;
    const float* Ap = A + (size_t)(bm + lrow) * K + lk;
    const float* Bp = B + (size_t)(bn + lrow) * K + lk;
    __half* AsW = &As[lrow * SAST + lk];
    __half* BsW = &Bs[lrow * SAST + lk];

    const int sub = lane >> 3;
    const int lr  = lane & 7;
    const int a_row_base = wm2 * 64 + ((sub & 1) * 8) + lr;
    const int a_col      = (sub >> 1) * 8;
    const int b_row_base = wn2 * 32 + ((sub >> 1) * 8) + lr;
    const int b_col      = (sub & 1) * 8;

    uint32_t a_addr[4], b_addr[2];
    {
        uint32_t as_base, bs_base;
        asm("{ .reg .u64 tmp; cvta.to.shared.u64 tmp, %1; cvt.u32.u64 %0, tmp; }"
            : "=r"(as_base) : "l"(As));
        asm("{ .reg .u64 tmp; cvta.to.shared.u64 tmp, %1; cvt.u32.u64 %0, tmp; }"
            : "=r"(bs_base) : "l"(Bs));
#pragma unroll
        for (int mt = 0; mt < 4; mt++)
            a_addr[mt] = as_base + 2 * ((a_row_base + mt * 16) * SAST + a_col);
#pragma unroll
        for (int g = 0; g < 2; g++)
            b_addr[g] = bs_base + 2 * ((b_row_base + g * 16) * SAST + b_col);
    }

    float acc[4][4][4];
#pragma unroll
    for (int mt = 0; mt < 4; mt++)
#pragma unroll
        for (int nt = 0; nt < 4; nt++)
#pragma unroll
            for (int c = 0; c < 4; c++) acc[mt][nt][c] = 0.0f;

    float4 ra0 = *(const float4*)(Ap);
    float4 ra1 = *(const float4*)(Ap + 4);
    float4 rb0 = *(const float4*)(Bp);
    float4 rb1 = *(const float4*)(Bp + 4);

    for (int k0 = 0; k0 < K; k0 += 16) {
        {
            uint4 av, bv;
            ((__half2*)&av)[0] = __floats2half2_rn(ra0.x, ra0.y);
            ((__half2*)&av)[1] = __floats2half2_rn(ra0.z, ra0.w);
            ((__half2*)&av)[2] = __floats2half2_rn(ra1.x, ra1.y);
            ((__half2*)&av)[3] = __floats2half2_rn(ra1.z, ra1.w);
            ((__half2*)&bv)[0] = __floats2half2_rn(rb0.x, rb0.y);
            ((__half2*)&bv)[1] = __floats2half2_rn(rb0.z, rb0.w);
            ((__half2*)&bv)[2] = __floats2half2_rn(rb1.x, rb1.y);
            ((__half2*)&bv)[3] = __floats2half2_rn(rb1.z, rb1.w);
            *(uint4*)AsW = av;
            *(uint4*)BsW = bv;
        }
        __syncthreads();

        if (k0 + 16 < K) {
            ra0 = *(const float4*)(Ap + k0 + 16);
            ra1 = *(const float4*)(Ap + k0 + 20);
            rb0 = *(const float4*)(Bp + k0 + 16);
            rb1 = *(const float4*)(Bp + k0 + 20);
        }

        uint32_t af[4][4];
#pragma unroll
        for (int mt = 0; mt < 4; mt++) {
            asm volatile(
                "ldmatrix.sync.aligned.m8n8.x4.shared.b16 {%0,%1,%2,%3}, [%4];"
                : "=r"(af[mt][0]), "=r"(af[mt][1]), "=r"(af[mt][2]), "=r"(af[mt][3])
                : "r"(a_addr[mt]));
        }
        uint32_t bf[4][2];
#pragma unroll
        for (int g = 0; g < 2; g++) {
            asm volatile(
                "ldmatrix.sync.aligned.m8n8.x4.shared.b16 {%0,%1,%2,%3}, [%4];"
                : "=r"(bf[g * 2][0]), "=r"(bf[g * 2][1]),
                  "=r"(bf[g * 2 + 1][0]), "=r"(bf[g * 2 + 1][1])
                : "r"(b_addr[g]));
        }

#pragma unroll
        for (int mt = 0; mt < 4; mt++)
#pragma unroll
            for (int nt = 0; nt < 4; nt++) {
                asm volatile(
                    "mma.sync.aligned.m16n8k16.row.col.f32.f16.f16.f32 "
                    "{%0,%1,%2,%3}, {%4,%5,%6,%7}, {%8,%9}, {%0,%1,%2,%3};"
                    : "+f"(acc[mt][nt][0]), "+f"(acc[mt][nt][1]),
                      "+f"(acc[mt][nt][2]), "+f"(acc[mt][nt][3])
                    : "r"(af[mt][0]), "r"(af[mt][1]), "r"(af[mt][2]), "r"(af[mt][3]),
                      "r"(bf[nt][0]), "r"(bf[nt][1]));
            }
        __syncthreads();
    }

    const int gr  = lane >> 2;
    const int gcs = lane & 3;
#pragma unroll
    for (int mt = 0; mt < 4; mt++) {
        const int m0 = bm + wm2 * 64 + mt * 16 + gr;
#pragma unroll
        for (int nt = 0; nt < 4; nt++) {
            const int n0 = bn + wn2 * 32 + nt * 8 + gcs * 2;
            const float bv0 = bias[n0];
            const float bv1 = bias[n0 + 1];
            float2 v01;
            v01.x = acc[mt][nt][0] + bv0;
            v01.y = acc[mt][nt][1] + bv1;
            *(float2*)&C[(size_t)m0 * N + n0] = v01;
            float2 v23;
            v23.x = acc[mt][nt][2] + bv0;
            v23.y = acc[mt][nt][3] + bv1;
            *(float2*)&C[(size_t)(m0 + 8) * N + n0] = v23;
        }
    }
}

// ----------------------------------------------------------------------------
// RoPE, REVERSE rotation (-sin), half-split pairs (j, j+32); Q and K fused.
// ----------------------------------------------------------------------------
__global__ void rope_negsin_qk(float* __restrict__ Q, float* __restrict__ K)
{
    float* X = blockIdx.y ? K : Q;
    const int idx = blockIdx.x * blockDim.x + threadIdx.x;
    const int total = BATCH * SEQ * NH * 32;
    if (idx >= total) return;
    const int j    = idx & 31;
    const int rest = idx >> 5;
    const int s    = (rest / NH) % SEQ;
    const size_t base = (size_t)rest * DH;

    const float inv_freq = expf(-((float)(2 * j) / (float)DH) * logf(10000.0f));
    const float ang = (float)s * inv_freq;
    float c, sn;
    sincosf(ang, &c, &sn);

    const float x1 = X[base + j];
    const float x2 = X[base + j + 32];
    X[base + j]      = x1 * c + x2 * sn;
    X[base + j + 32] = x2 * c - x1 * sn;
}

// ----------------------------------------------------------------------------
// FP16 tensor-core flash attention (FA2 fragment style).
// Grid (16 q-tiles, NH, BATCH), 128 threads = 4 warps; warp owns 16 q-rows.
// Q fragments in registers (scaled by 1/8); K/V tiles (64 keys) staged fp16 in
// smem with row stride 72 halves (conflict-free ldmatrix). Online softmax on
// S fragments in fp32 via quad shuffles; P repacked directly into A-fragments.
// ----------------------------------------------------------------------------
#define FW 72   // flash smem row stride (halves)

__global__ __launch_bounds__(128) void flash_attn_f16(
    const float* __restrict__ Q, const float* __restrict__ K,
    const float* __restrict__ V, float* __restrict__ O)
{
    __shared__ __align__(16) __half Qs[64 * FW];
    __shared__ __align__(16) __half Ks[64 * FW];
    __shared__ __align__(16) __half Vs[64 * FW];

    const int qt = blockIdx.x;
    const int h  = blockIdx.y;
    const int b  = blockIdx.z;
    const int t  = threadIdx.x;
    const int warp = t >> 5;
    const int lane = t & 31;
    const int gr   = lane >> 2;
    const int gc   = lane & 3;
    const int sub  = lane >> 3;
    const int lr   = lane & 7;

    const int q0 = qt * 64;
    const int hcol = h * DH;
    const size_t seq_base = (size_t)b * SEQ * DIM + hcol;

    uint32_t qs_base, ks_base, vs_base;
    asm("{ .reg .u64 tmp; cvta.to.shared.u64 tmp, %1; cvt.u32.u64 %0, tmp; }"
        : "=r"(qs_base) : "l"(Qs));
    asm("{ .reg .u64 tmp; cvta.to.shared.u64 tmp, %1; cvt.u32.u64 %0, tmp; }"
        : "=r"(ks_base) : "l"(Ks));
    asm("{ .reg .u64 tmp; cvta.to.shared.u64 tmp, %1; cvt.u32.u64 %0, tmp; }"
        : "=r"(vs_base) : "l"(Vs));

    // Stage Q tile (64x64), scaled by 1/8, fp32 -> fp16
    for (int u = t; u < 64 * 8; u += 128) {
        const int row = u >> 3;
        const int c   = (u & 7) * 8;
        const float4 v0 = *(const float4*)&Q[seq_base + (size_t)(q0 + row) * DIM + c];
        const float4 v1 = *(const float4*)&Q[seq_base + (size_t)(q0 + row) * DIM + c + 4];
        uint4 hv;
        ((__half2*)&hv)[0] = __floats2half2_rn(v0.x * 0.125f, v0.y * 0.125f);
        ((__half2*)&hv)[1] = __floats2half2_rn(v0.z * 0.125f, v0.w * 0.125f);
        ((__half2*)&hv)[2] = __floats2half2_rn(v1.x * 0.125f, v1.y * 0.125f);
        ((__half2*)&hv)[3] = __floats2half2_rn(v1.z * 0.125f, v1.w * 0.125f);
        *(uint4*)&Qs[row * FW + c] = hv;
    }
    __syncthreads();

    // Q fragments: [kc][4], rows warp*16..+15, dims kc*16..+15
    uint32_t qf[4][4];
#pragma unroll
    for (int kc = 0; kc < 4; kc++) {
        const int row = warp * 16 + (sub & 1) * 8 + lr;
        const int col = kc * 16 + (sub >> 1) * 8;
        const uint32_t addr = qs_base + 2 * (row * FW + col);
        asm volatile(
            "ldmatrix.sync.aligned.m8n8.x4.shared.b16 {%0,%1,%2,%3}, [%4];"
            : "=r"(qf[kc][0]), "=r"(qf[kc][1]), "=r"(qf[kc][2]), "=r"(qf[kc][3])
            : "r"(addr));
    }

    float m0 = -1e30f, m1 = -1e30f, l0 = 0.0f, l1 = 0.0f;
    float o[8][4];
#pragma unroll
    for (int nt = 0; nt < 8; nt++)
#pragma unroll
        for (int c = 0; c < 4; c++) o[nt][c] = 0.0f;

    for (int kt = 0; kt < SEQ; kt += 64) {
        __syncthreads();
        // Stage K and V tiles (64 keys x 64 dims), fp32 -> fp16
        for (int u = t; u < 64 * 8; u += 128) {
            const int row = u >> 3;
            const int c   = (u & 7) * 8;
            const size_t g = seq_base + (size_t)(kt + row) * DIM + c;
            const float4 k0v = *(const float4*)&K[g];
            const float4 k1v = *(const float4*)&K[g + 4];
            uint4 hk;
            ((__half2*)&hk)[0] = __floats2half2_rn(k0v.x, k0v.y);
            ((__half2*)&hk)[1] = __floats2half2_rn(k0v.z, k0v.w);
            ((__half2*)&hk)[2] = __floats2half2_rn(k1v.x, k1v.y);
            ((__half2*)&hk)[3] = __floats2half2_rn(k1v.z, k1v.w);
            *(uint4*)&Ks[row * FW + c] = hk;
            const float4 v0v = *(const float4*)&V[g];
            const float4 v1v = *(const float4*)&V[g + 4];
            uint4 hv;
            ((__half2*)&hv)[0] = __floats2half2_rn(v0v.x, v0v.y);
            ((__half2*)&hv)[1] = __floats2half2_rn(v0v.z, v0v.w);
            ((__half2*)&hv)[2] = __floats2half2_rn(v1v.x, v1v.y);
            ((__half2*)&hv)[3] = __floats2half2_rn(v1v.z, v1v.w);
            *(uint4*)&Vs[row * FW + c] = hv;
        }
        __syncthreads();

        // S = Q K^T (16 q-rows x 64 keys per warp), fp32 accum
        float s[8][4];
#pragma unroll
        for (int nt = 0; nt < 8; nt++)
#pragma unroll
            for (int c = 0; c < 4; c++) s[nt][c] = 0.0f;

#pragma unroll
        for (int kc = 0; kc < 4; kc++) {
            uint32_t kf[8][2];
#pragma unroll
            for (int p = 0; p < 4; p++) {
                // matrices: m0=(keys p*16+0-7, dims lo), m1=(same keys, dims hi),
                //           m2=(keys p*16+8-15, dims lo), m3=(keys hi, dims hi)
                const int row = p * 16 + (sub >> 1) * 8 + lr;
                const int col = kc * 16 + (sub & 1) * 8;
                const uint32_t addr = ks_base + 2 * (row * FW + col);
                asm volatile(
                    "ldmatrix.sync.aligned.m8n8.x4.shared.b16 {%0,%1,%2,%3}, [%4];"
                    : "=r"(kf[p * 2][0]), "=r"(kf[p * 2][1]),
                      "=r"(kf[p * 2 + 1][0]), "=r"(kf[p * 2 + 1][1])
                    : "r"(addr));
            }
#pragma unroll
            for (int nt = 0; nt < 8; nt++) {
                asm volatile(
                    "mma.sync.aligned.m16n8k16.row.col.f32.f16.f16.f32 "
                    "{%0,%1,%2,%3}, {%4,%5,%6,%7}, {%8,%9}, {%0,%1,%2,%3};"
                    : "+f"(s[nt][0]), "+f"(s[nt][1]), "+f"(s[nt][2]), "+f"(s[nt][3])
                    : "r"(qf[kc][0]), "r"(qf[kc][1]), "r"(qf[kc][2]), "r"(qf[kc][3]),
                      "r"(kf[nt][0]), "r"(kf[nt][1]));
            }
        }

        // Online softmax on fragments.
        // Thread rows: r0 = warp*16+gr (c0,c1), r1 = r0+8 (c2,c3).
        float mx0 = -1e30f, mx1 = -1e30f;
#pragma unroll
        for (int nt = 0; nt < 8; nt++) {
            mx0 = fmaxf(mx0, fmaxf(s[nt][0], s[nt][1]));
            mx1 = fmaxf(mx1, fmaxf(s[nt][2], s[nt][3]));
        }
        mx0 = fmaxf(mx0, __shfl_xor_sync(0xffffffffu, mx0, 1));
        mx0 = fmaxf(mx0, __shfl_xor_sync(0xffffffffu, mx0, 2));
        mx1 = fmaxf(mx1, __shfl_xor_sync(0xffffffffu, mx1, 1));
        mx1 = fmaxf(mx1, __shfl_xor_sync(0xffffffffu, mx1, 2));

        const float nm0 = fmaxf(m0, mx0);
        const float nm1 = fmaxf(m1, mx1);
        const float corr0 = __expf(m0 - nm0);
        const float corr1 = __expf(m1 - nm1);
        m0 = nm0;
        m1 = nm1;

        float ps0 = 0.0f, ps1 = 0.0f;
#pragma unroll
        for (int nt = 0; nt < 8; nt++) {
            s[nt][0] = __expf(s[nt][0] - nm0);
            s[nt][1] = __expf(s[nt][1] - nm0);
            s[nt][2] = __expf(s[nt][2] - nm1);
            s[nt][3] = __expf(s[nt][3] - nm1);
            ps0 += s[nt][0] + s[nt][1];
            ps1 += s[nt][2] + s[nt][3];
        }
        ps0 += __shfl_xor_sync(0xffffffffu, ps0, 1);
        ps0 += __shfl_xor_sync(0xffffffffu, ps0, 2);
        ps1 += __shfl_xor_sync(0xffffffffu, ps1, 1);
        ps1 += __shfl_xor_sync(0xffffffffu, ps1, 2);
        l0 = l0 * corr0 + ps0;
        l1 = l1 * corr1 + ps1;

#pragma unroll
        for (int nt = 0; nt < 8; nt++) {
            o[nt][0] *= corr0;
            o[nt][1] *= corr0;
            o[nt][2] *= corr1;
            o[nt][3] *= corr1;
        }

        // O += P V : P fragments straight from s[][]; V via ldmatrix.trans
#pragma unroll
        for (int kc = 0; kc < 4; kc++) {
            uint32_t pa[4];
            {
                __half2 h0 = __floats2half2_rn(s[2 * kc][0], s[2 * kc][1]);
                __half2 h1 = __floats2half2_rn(s[2 * kc][2], s[2 * kc][3]);
                __half2 h2 = __floats2half2_rn(s[2 * kc + 1][0], s[2 * kc + 1][1]);
                __half2 h3 = __floats2half2_rn(s[2 * kc + 1][2], s[2 * kc + 1][3]);
                pa[0] = *(uint32_t*)&h0;
                pa[1] = *(uint32_t*)&h1;
                pa[2] = *(uint32_t*)&h2;
                pa[3] = *(uint32_t*)&h3;
            }
            uint32_t vb[8][2];
#pragma unroll
            for (int pd = 0; pd < 4; pd++) {
                // trans matrices: m0=(keys kc*16+0-7, d pd*16+0-7), m1=(keys hi, d lo),
                //                 m2=(keys lo, d hi), m3=(keys hi, d hi)
                const int row = kc * 16 + (sub & 1) * 8 + lr;
                const int col = pd * 16 + (sub >> 1) * 8;
                const uint32_t addr = vs_base + 2 * (row * FW + col);
                asm volatile(
                    "ldmatrix.sync.aligned.m8n8.x4.trans.shared.b16 {%0,%1,%2,%3}, [%4];"
                    : "=r"(vb[pd * 2][0]), "=r"(vb[pd * 2][1]),
                      "=r"(vb[pd * 2 + 1][0]), "=r"(vb[pd * 2 + 1][1])
                    : "r"(addr));
            }
#pragma unroll
            for (int nt = 0; nt < 8; nt++) {
                asm volatile(
                    "mma.sync.aligned.m16n8k16.row.col.f32.f16.f16.f32 "
                    "{%0,%1,%2,%3}, {%4,%5,%6,%7}, {%8,%9}, {%0,%1,%2,%3};"
                    : "+f"(o[nt][0]), "+f"(o[nt][1]), "+f"(o[nt][2]), "+f"(o[nt][3])
                    : "r"(pa[0]), "r"(pa[1]), "r"(pa[2]), "r"(pa[3]),
                      "r"(vb[nt][0]), "r"(vb[nt][1]));
            }
        }
    }

    // Normalize and store O (fp32)
    const float inv0 = 1.0f / l0;
    const float inv1 = 1.0f / l1;
    const size_t orow0 = seq_base + (size_t)(q0 + warp * 16 + gr) * DIM;
    const size_t orow1 = orow0 + (size_t)8 * DIM;
#pragma unroll
    for (int nt = 0; nt < 8; nt++) {
        const int n0 = nt * 8 + gc * 2;
        float2 w0;
        w0.x = o[nt][0] * inv0;
        w0.y = o[nt][1] * inv0;
        *(float2*)&O[orow0 + n0] = w0;
        float2 w1;
        w1.x = o[nt][2] * inv1;
        w1.y = o[nt][3] * inv1;
        *(float2*)&O[orow1 + n0] = w1;
    }
}

// ----------------------------------------------------------------------------
// Launch — strict dict-order input mapping: x, Wq, bq, Wk, bk, Wv, bv, Wo, bo
// ----------------------------------------------------------------------------
extern "C" void kernel_launch(void* const* d_in, const int* in_sizes, int n_in,
                              void* d_out, int out_size)
{
    (void)in_sizes; (void)n_in; (void)out_size;
    const float* x  = (const float*)d_in[0];
    const float* Wq = (const float*)d_in[1];
    const float* bq = (const float*)d_in[2];
    const float* Wk = (const float*)d_in[3];
    const float* bk = (const float*)d_in[4];
    const float* Wv = (const float*)d_in[5];
    const float* bv = (const float*)d_in[6];
    const float* Wo = (const float*)d_in[7];
    const float* bo = (const float*)d_in[8];
    float* out = (float*)d_out;

    float *Q, *K, *V, *O;
    cudaGetSymbolAddress((void**)&Q, g_Q);
    cudaGetSymbolAddress((void**)&K, g_K);
    cudaGetSymbolAddress((void**)&V, g_V);
    cudaGetSymbolAddress((void**)&O, g_O);

    const dim3 g3(DIM / 128, MROWS / 128, 3);
    gemm3_f16_nt_bias<<<g3, 256>>>(x, Wq, Wk, Wv, bq, bk, bv, Q, K, V,
                                   MROWS, DIM, DIM);

    const int rope_threads = BATCH * SEQ * NH * 32;
    const dim3 rgrid((rope_threads + 255) / 256, 2);
    rope_negsin_qk<<<rgrid, 256>>>(Q, K);

    const dim3 agrid(SEQ / 64, NH, BATCH);
    flash_attn_f16<<<agrid, 128>>>(Q, K, V, O);

    const dim3 g1(DIM / 128, MROWS / 128, 1);
    gemm3_f16_nt_bias<<<g1, 256>>>(O, Wo, Wo, Wo, bo, bo, bo, out, out, out,
                                   MROWS, DIM, DIM);
}

// round 14
// speedup vs baseline: 3.5832x; 1.2773x over previous
#include <cuda_runtime.h>
#include <cuda_fp16.h>
#include <math.h>
#include <stdint.h>

// Problem constants
#define BATCH 4
#define SEQ   1024
#define DIM   1024
#define NH    16
#define DH    64
#define MROWS (BATCH * SEQ)   // 4096

// Scratch (allocation-free rule: __device__ globals)
__device__ float  g_Q[MROWS * DIM];
__device__ float  g_K[MROWS * DIM];
__device__ float  g_V[MROWS * DIM];
__device__ __half g_Oh[MROWS * DIM];
__device__ __half g_xh[MROWS * DIM];
__device__ __half g_Wqh[DIM * DIM];
__device__ __half g_Wkh[DIM * DIM];
__device__ __half g_Wvh[DIM * DIM];
__device__ __half g_Woh[DIM * DIM];

// ----------------------------------------------------------------------------
// fp32 -> fp16 conversion, 8 floats per thread, vectorized.
// ----------------------------------------------------------------------------
__global__ void f32_to_f16(const float* __restrict__ src, __half* __restrict__ dst, int n)
{
    const int i = (blockIdx.x * blockDim.x + threadIdx.x) * 8;
    if (i >= n) return;
    const float4 v0 = *(const float4*)(src + i);
    const float4 v1 = *(const float4*)(src + i + 4);
    uint4 h;
    ((__half2*)&h)[0] = __floats2half2_rn(v0.x, v0.y);
    ((__half2*)&h)[1] = __floats2half2_rn(v0.z, v0.w);
    ((__half2*)&h)[2] = __floats2half2_rn(v1.x, v1.y);
    ((__half2*)&h)[3] = __floats2half2_rn(v1.z, v1.w);
    *(uint4*)(dst + i) = h;
}

// ----------------------------------------------------------------------------
// FP16 NT GEMM with bias, cp.async 4-stage pipeline, fused over blockIdx.z.
// C[m,n] = sum_k A[m,k]*Wz[n,k] + biasz[n]  (A, W fp16; C fp32)
// Tile 128x128x16, 8 warps (64m x 32n per warp), ldmatrix + mma.m16n8k16.
// Smem: 4 stages x (A,B) 128 rows x 24-half stride = 48KB exactly.
// ----------------------------------------------------------------------------
#define SAST 24                 // smem row stride in halves
#define STG_H (128 * SAST)      // halves per stage per operand
#define STG_B (STG_H * 2)       // bytes per stage per operand

__global__ __launch_bounds__(256, 2) void gemm3h_nt_bias(
    const __half* __restrict__ A,
    const __half* __restrict__ W0, const __half* __restrict__ W1, const __half* __restrict__ W2,
    const float* __restrict__ b0, const float* __restrict__ b1, const float* __restrict__ b2,
    float* __restrict__ C0, float* __restrict__ C1, float* __restrict__ C2,
    int M, int N, int K)
{
    const int z = blockIdx.z;
    const __half* B   = (z == 0) ? W0 : (z == 1) ? W1 : W2;
    const float* bias = (z == 0) ? b0 : (z == 1) ? b1 : b2;
    float* C          = (z == 0) ? C0 : (z == 1) ? C1 : C2;

    __shared__ __align__(16) __half As[4][STG_H];
    __shared__ __align__(16) __half Bs[4][STG_H];

    const int bm   = blockIdx.y * 128;
    const int bn   = blockIdx.x * 128;
    const int t    = threadIdx.x;
    const int warp = t >> 5;
    const int lane = t & 31;
    const int wm2  = warp & 1;
    const int wn2  = warp >> 1;

    // cp.async loader mapping: row (t>>1), 8-half chunk (t&1)
    const int lrow = t >> 1;
    const int lk   = (t & 1) * 8;
    const __half* Ap = A + (size_t)(bm + lrow) * K + lk;
    const __half* Bp = B + (size_t)(bn + lrow) * K + lk;

    uint32_t as_base, bs_base;
    asm("{ .reg .u64 tmp; cvta.to.shared.u64 tmp, %1; cvt.u32.u64 %0, tmp; }"
        : "=r"(as_base) : "l"(&As[0][0]));
    asm("{ .reg .u64 tmp; cvta.to.shared.u64 tmp, %1; cvt.u32.u64 %0, tmp; }"
        : "=r"(bs_base) : "l"(&Bs[0][0]));
    const uint32_t a_st = as_base + 2 * (lrow * SAST + lk);
    const uint32_t b_st = bs_base + 2 * (lrow * SAST + lk);

    // ldmatrix source addresses (stage 0)
    const int sub = lane >> 3;
    const int lr  = lane & 7;
    uint32_t a_addr[4], b_addr[2];
#pragma unroll
    for (int mt = 0; mt < 4; mt++) {
        const int row = wm2 * 64 + mt * 16 + (sub & 1) * 8 + lr;
        const int col = (sub >> 1) * 8;
        a_addr[mt] = as_base + 2 * (row * SAST + col);
    }
#pragma unroll
    for (int g = 0; g < 2; g++) {
        const int row = wn2 * 32 + g * 16 + (sub >> 1) * 8 + lr;
        const int col = (sub & 1) * 8;
        b_addr[g] = bs_base + 2 * (row * SAST + col);
    }

    float acc[4][4][4];
#pragma unroll
    for (int mt = 0; mt < 4; mt++)
#pragma unroll
        for (int nt = 0; nt < 4; nt++)
#pragma unroll
            for (int c = 0; c < 4; c++) acc[mt][nt][c] = 0.0f;

    const int NITER = K / 16;   // 64

    // Prologue: stages 0..2
#pragma unroll
    for (int s = 0; s < 3; s++) {
        asm volatile("cp.async.ca.shared.global [%0], [%1], 16;"
                     :: "r"(a_st + s * STG_B), "l"(Ap + s * 16));
        asm volatile("cp.async.ca.shared.global [%0], [%1], 16;"
                     :: "r"(b_st + s * STG_B), "l"(Bp + s * 16));
        asm volatile("cp.async.commit_group;");
    }

    for (int i = 0; i < NITER; i++) {
        asm volatile("cp.async.wait_group 2;");
        __syncthreads();

        // Issue stage i+3 into slot (i+3)&3 (slot of stage i-1; safe after sync)
        if (i + 3 < NITER) {
            const int slot = (i + 3) & 3;
            asm volatile("cp.async.ca.shared.global [%0], [%1], 16;"
                         :: "r"(a_st + slot * STG_B), "l"(Ap + (i + 3) * 16));
            asm volatile("cp.async.ca.shared.global [%0], [%1], 16;"
                         :: "r"(b_st + slot * STG_B), "l"(Bp + (i + 3) * 16));
        }
        asm volatile("cp.async.commit_group;");

        const uint32_t soff = (uint32_t)((i & 3) * STG_B);

        uint32_t af[4][4];
#pragma unroll
        for (int mt = 0; mt < 4; mt++) {
            asm volatile(
                "ldmatrix.sync.aligned.m8n8.x4.shared.b16 {%0,%1,%2,%3}, [%4];"
                : "=r"(af[mt][0]), "=r"(af[mt][1]), "=r"(af[mt][2]), "=r"(af[mt][3])
                : "r"(a_addr[mt] + soff));
        }
        uint32_t bf[4][2];
#pragma unroll
        for (int g = 0; g < 2; g++) {
            asm volatile(
                "ldmatrix.sync.aligned.m8n8.x4.shared.b16 {%0,%1,%2,%3}, [%4];"
                : "=r"(bf[g * 2][0]), "=r"(bf[g * 2][1]),
                  "=r"(bf[g * 2 + 1][0]), "=r"(bf[g * 2 + 1][1])
                : "r"(b_addr[g] + soff));
        }

#pragma unroll
        for (int mt = 0; mt < 4; mt++)
#pragma unroll
            for (int nt = 0; nt < 4; nt++) {
                asm volatile(
                    "mma.sync.aligned.m16n8k16.row.col.f32.f16.f16.f32 "
                    "{%0,%1,%2,%3}, {%4,%5,%6,%7}, {%8,%9}, {%0,%1,%2,%3};"
                    : "+f"(acc[mt][nt][0]), "+f"(acc[mt][nt][1]),
                      "+f"(acc[mt][nt][2]), "+f"(acc[mt][nt][3])
                    : "r"(af[mt][0]), "r"(af[mt][1]), "r"(af[mt][2]), "r"(af[mt][3]),
                      "r"(bf[nt][0]), "r"(bf[nt][1]));
            }
    }

    const int gr  = lane >> 2;
    const int gcs = lane & 3;
#pragma unroll
    for (int mt = 0; mt < 4; mt++) {
        const int m0 = bm + wm2 * 64 + mt * 16 + gr;
#pragma unroll
        for (int nt = 0; nt < 4; nt++) {
            const int n0 = bn + wn2 * 32 + nt * 8 + gcs * 2;
            const float bv0 = bias[n0];
            const float bv1 = bias[n0 + 1];
            float2 v01;
            v01.x = acc[mt][nt][0] + bv0;
            v01.y = acc[mt][nt][1] + bv1;
            *(float2*)&C[(size_t)m0 * N + n0] = v01;
            float2 v23;
            v23.x = acc[mt][nt][2] + bv0;
            v23.y = acc[mt][nt][3] + bv1;
            *(float2*)&C[(size_t)(m0 + 8) * N + n0] = v23;
        }
    }
}

// ----------------------------------------------------------------------------
// RoPE, REVERSE rotation (-sin), half-split pairs (j, j+32); Q and K fused.
// ----------------------------------------------------------------------------
__global__ void rope_negsin_qk(float* __restrict__ Q, float* __restrict__ K)
{
    float* X = blockIdx.y ? K : Q;
    const int idx = blockIdx.x * blockDim.x + threadIdx.x;
    const int total = BATCH * SEQ * NH * 32;
    if (idx >= total) return;
    const int j    = idx & 31;
    const int rest = idx >> 5;
    const int s    = (rest / NH) % SEQ;
    const size_t base = (size_t)rest * DH;

    const float inv_freq = expf(-((float)(2 * j) / (float)DH) * logf(10000.0f));
    const float ang = (float)s * inv_freq;
    float c, sn;
    sincosf(ang, &c, &sn);

    const float x1 = X[base + j];
    const float x2 = X[base + j + 32];
    X[base + j]      = x1 * c + x2 * sn;
    X[base + j + 32] = x2 * c - x1 * sn;
}

// ----------------------------------------------------------------------------
// FP16 tensor-core flash attention (FA2 fragment style), writes fp16 Oh.
// ----------------------------------------------------------------------------
#define FW 72   // flash smem row stride (halves)

__global__ __launch_bounds__(128) void flash_attn_f16(
    const float* __restrict__ Q, const float* __restrict__ K,
    const float* __restrict__ V, __half* __restrict__ Oh)
{
    __shared__ __align__(16) __half Qs[64 * FW];
    __shared__ __align__(16) __half Ks[64 * FW];
    __shared__ __align__(16) __half Vs[64 * FW];

    const int qt = blockIdx.x;
    const int h  = blockIdx.y;
    const int b  = blockIdx.z;
    const int t  = threadIdx.x;
    const int warp = t >> 5;
    const int lane = t & 31;
    const int gr   = lane >> 2;
    const int gc   = lane & 3;
    const int sub  = lane >> 3;
    const int lr   = lane & 7;

    const int q0 = qt * 64;
    const int hcol = h * DH;
    const size_t seq_base = (size_t)b * SEQ * DIM + hcol;

    uint32_t qs_base, ks_base, vs_base;
    asm("{ .reg .u64 tmp; cvta.to.shared.u64 tmp, %1; cvt.u32.u64 %0, tmp; }"
        : "=r"(qs_base) : "l"(Qs));
    asm("{ .reg .u64 tmp; cvta.to.shared.u64 tmp, %1; cvt.u32.u64 %0, tmp; }"
        : "=r"(ks_base) : "l"(Ks));
    asm("{ .reg .u64 tmp; cvta.to.shared.u64 tmp, %1; cvt.u32.u64 %0, tmp; }"
        : "=r"(vs_base) : "l"(Vs));

    for (int u = t; u < 64 * 8; u += 128) {
        const int row = u >> 3;
        const int c   = (u & 7) * 8;
        const float4 v0 = *(const float4*)&Q[seq_base + (size_t)(q0 + row) * DIM + c];
        const float4 v1 = *(const float4*)&Q[seq_base + (size_t)(q0 + row) * DIM + c + 4];
        uint4 hv;
        ((__half2*)&hv)[0] = __floats2half2_rn(v0.x * 0.125f, v0.y * 0.125f);
        ((__half2*)&hv)[1] = __floats2half2_rn(v0.z * 0.125f, v0.w * 0.125f);
        ((__half2*)&hv)[2] = __floats2half2_rn(v1.x * 0.125f, v1.y * 0.125f);
        ((__half2*)&hv)[3] = __floats2half2_rn(v1.z * 0.125f, v1.w * 0.125f);
        *(uint4*)&Qs[row * FW + c] = hv;
    }
    __syncthreads();

    uint32_t qf[4][4];
#pragma unroll
    for (int kc = 0; kc < 4; kc++) {
        const int row = warp * 16 + (sub & 1) * 8 + lr;
        const int col = kc * 16 + (sub >> 1) * 8;
        const uint32_t addr = qs_base + 2 * (row * FW + col);
        asm volatile(
            "ldmatrix.sync.aligned.m8n8.x4.shared.b16 {%0,%1,%2,%3}, [%4];"
            : "=r"(qf[kc][0]), "=r"(qf[kc][1]), "=r"(qf[kc][2]), "=r"(qf[kc][3])
            : "r"(addr));
    }

    float m0 = -1e30f, m1 = -1e30f, l0 = 0.0f, l1 = 0.0f;
    float o[8][4];
#pragma unroll
    for (int nt = 0; nt < 8; nt++)
#pragma unroll
        for (int c = 0; c < 4; c++) o[nt][c] = 0.0f;

    for (int kt = 0; kt < SEQ; kt += 64) {
        __syncthreads();
        for (int u = t; u < 64 * 8; u += 128) {
            const int row = u >> 3;
            const int c   = (u & 7) * 8;
            const size_t g = seq_base + (size_t)(kt + row) * DIM + c;
            const float4 k0v = *(const float4*)&K[g];
            const float4 k1v = *(const float4*)&K[g + 4];
            uint4 hk;
            ((__half2*)&hk)[0] = __floats2half2_rn(k0v.x, k0v.y);
            ((__half2*)&hk)[1] = __floats2half2_rn(k0v.z, k0v.w);
            ((__half2*)&hk)[2] = __floats2half2_rn(k1v.x, k1v.y);
            ((__half2*)&hk)[3] = __floats2half2_rn(k1v.z, k1v.w);
            *(uint4*)&Ks[row * FW + c] = hk;
            const float4 v0v = *(const float4*)&V[g];
            const float4 v1v = *(const float4*)&V[g + 4];
            uint4 hv;
            ((__half2*)&hv)[0] = __floats2half2_rn(v0v.x, v0v.y);
            ((__half2*)&hv)[1] = __floats2half2_rn(v0v.z, v0v.w);
            ((__half2*)&hv)[2] = __floats2half2_rn(v1v.x, v1v.y);
            ((__half2*)&hv)[3] = __floats2half2_rn(v1v.z, v1v.w);
            *(uint4*)&Vs[row * FW + c] = hv;
        }
        __syncthreads();

        float s[8][4];
#pragma unroll
        for (int nt = 0; nt < 8; nt++)
#pragma unroll
            for (int c = 0; c < 4; c++) s[nt][c] = 0.0f;

#pragma unroll
        for (int kc = 0; kc < 4; kc++) {
            uint32_t kf[8][2];
#pragma unroll
            for (int p = 0; p < 4; p++) {
                const int row = p * 16 + (sub >> 1) * 8 + lr;
                const int col = kc * 16 + (sub & 1) * 8;
                const uint32_t addr = ks_base + 2 * (row * FW + col);
                asm volatile(
                    "ldmatrix.sync.aligned.m8n8.x4.shared.b16 {%0,%1,%2,%3}, [%4];"
                    : "=r"(kf[p * 2][0]), "=r"(kf[p * 2][1]),
                      "=r"(kf[p * 2 + 1][0]), "=r"(kf[p * 2 + 1][1])
                    : "r"(addr));
            }
#pragma unroll
            for (int nt = 0; nt < 8; nt++) {
                asm volatile(
                    "mma.sync.aligned.m16n8k16.row.col.f32.f16.f16.f32 "
                    "{%0,%1,%2,%3}, {%4,%5,%6,%7}, {%8,%9}, {%0,%1,%2,%3};"
                    : "+f"(s[nt][0]), "+f"(s[nt][1]), "+f"(s[nt][2]), "+f"(s[nt][3])
                    : "r"(qf[kc][0]), "r"(qf[kc][1]), "r"(qf[kc][2]), "r"(qf[kc][3]),
                      "r"(kf[nt][0]), "r"(kf[nt][1]));
            }
        }

        float mx0 = -1e30f, mx1 = -1e30f;
#pragma unroll
        for (int nt = 0; nt < 8; nt++) {
            mx0 = fmaxf(mx0, fmaxf(s[nt][0], s[nt][1]));
            mx1 = fmaxf(mx1, fmaxf(s[nt][2], s[nt][3]));
        }
        mx0 = fmaxf(mx0, __shfl_xor_sync(0xffffffffu, mx0, 1));
        mx0 = fmaxf(mx0, __shfl_xor_sync(0xffffffffu, mx0, 2));
        mx1 = fmaxf(mx1, __shfl_xor_sync(0xffffffffu, mx1, 1));
        mx1 = fmaxf(mx1, __shfl_xor_sync(0xffffffffu, mx1, 2));

        const float nm0 = fmaxf(m0, mx0);
        const float nm1 = fmaxf(m1, mx1);
        const float corr0 = __expf(m0 - nm0);
        const float corr1 = __expf(m1 - nm1);
        m0 = nm0;
        m1 = nm1;

        float ps0 = 0.0f, ps1 = 0.0f;
#pragma unroll
        for (int nt = 0; nt < 8; nt++) {
            s[nt][0] = __expf(s[nt][0] - nm0);
            s[nt][1] = __expf(s[nt][1] - nm0);
            s[nt][2] = __expf(s[nt][2] - nm1);
            s[nt][3] = __expf(s[nt][3] - nm1);
            ps0 += s[nt][0] + s[nt][1];
            ps1 += s[nt][2] + s[nt][3];
        }
        ps0 += __shfl_xor_sync(0xffffffffu, ps0, 1);
        ps0 += __shfl_xor_sync(0xffffffffu, ps0, 2);
        ps1 += __shfl_xor_sync(0xffffffffu, ps1, 1);
        ps1 += __shfl_xor_sync(0xffffffffu, ps1, 2);
        l0 = l0 * corr0 + ps0;
        l1 = l1 * corr1 + ps1;

#pragma unroll
        for (int nt = 0; nt < 8; nt++) {
            o[nt][0] *= corr0;
            o[nt][1] *= corr0;
            o[nt][2] *= corr1;
            o[nt][3] *= corr1;
        }

#pragma unroll
        for (int kc = 0; kc < 4; kc++) {
            uint32_t pa[4];
            {
                __half2 h0 = __floats2half2_rn(s[2 * kc][0], s[2 * kc][1]);
                __half2 h1 = __floats2half2_rn(s[2 * kc][2], s[2 * kc][3]);
                __half2 h2 = __floats2half2_rn(s[2 * kc + 1][0], s[2 * kc + 1][1]);
                __half2 h3 = __floats2half2_rn(s[2 * kc + 1][2], s[2 * kc + 1][3]);
                pa[0] = *(uint32_t*)&h0;
                pa[1] = *(uint32_t*)&h1;
                pa[2] = *(uint32_t*)&h2;
                pa[3] = *(uint32_t*)&h3;
            }
            uint32_t vb[8][2];
#pragma unroll
            for (int pd = 0; pd < 4; pd++) {
                const int row = kc * 16 + (sub & 1) * 8 + lr;
                const int col = pd * 16 + (sub >> 1) * 8;
                const uint32_t addr = vs_base + 2 * (row * FW + col);
                asm volatile(
                    "ldmatrix.sync.aligned.m8n8.x4.trans.shared.b16 {%0,%1,%2,%3}, [%4];"
                    : "=r"(vb[pd * 2][0]), "=r"(vb[pd * 2][1]),
                      "=r"(vb[pd * 2 + 1][0]), "=r"(vb[pd * 2 + 1][1])
                    : "r"(addr));
            }
#pragma unroll
            for (int nt = 0; nt < 8; nt++) {
                asm volatile(
                    "mma.sync.aligned.m16n8k16.row.col.f32.f16.f16.f32 "
                    "{%0,%1,%2,%3}, {%4,%5,%6,%7}, {%8,%9}, {%0,%1,%2,%3};"
                    : "+f"(o[nt][0]), "+f"(o[nt][1]), "+f"(o[nt][2]), "+f"(o[nt][3])
                    : "r"(pa[0]), "r"(pa[1]), "r"(pa[2]), "r"(pa[3]),
                      "r"(vb[nt][0]), "r"(vb[nt][1]));
            }
        }
    }

    // Normalize and store O as fp16 (input to o-proj GEMM)
    const float inv0 = 1.0f / l0;
    const float inv1 = 1.0f / l1;
    const size_t orow0 = seq_base + (size_t)(q0 + warp * 16 + gr) * DIM;
    const size_t orow1 = orow0 + (size_t)8 * DIM;
#pragma unroll
    for (int nt = 0; nt < 8; nt++) {
        const int n0 = nt * 8 + gc * 2;
        __half2 w0 = __floats2half2_rn(o[nt][0] * inv0, o[nt][1] * inv0);
        __half2 w1 = __floats2half2_rn(o[nt][2] * inv1, o[nt][3] * inv1);
        *(uint32_t*)&Oh[orow0 + n0] = *(uint32_t*)&w0;
        *(uint32_t*)&Oh[orow1 + n0] = *(uint32_t*)&w1;
    }
}

// ----------------------------------------------------------------------------
// Launch — strict dict-order input mapping: x, Wq, bq, Wk, bk, Wv, bv, Wo, bo
// ----------------------------------------------------------------------------
extern "C" void kernel_launch(void* const* d_in, const int* in_sizes, int n_in,
                              void* d_out, int out_size)
{
    (void)in_sizes; (void)n_in; (void)out_size;
    const float* x  = (const float*)d_in[0];
    const float* Wq = (const float*)d_in[1];
    const float* bq = (const float*)d_in[2];
    const float* Wk = (const float*)d_in[3];
    const float* bk = (const float*)d_in[4];
    const float* Wv = (const float*)d_in[5];
    const float* bv = (const float*)d_in[6];
    const float* Wo = (const float*)d_in[7];
    const float* bo = (const float*)d_in[8];
    float* out = (float*)d_out;

    float *Q, *K, *V;
    __half *Oh, *xh, *Wqh, *Wkh, *Wvh, *Woh;
    cudaGetSymbolAddress((void**)&Q,   g_Q);
    cudaGetSymbolAddress((void**)&K,   g_K);
    cudaGetSymbolAddress((void**)&V,   g_V);
    cudaGetSymbolAddress((void**)&Oh,  g_Oh);
    cudaGetSymbolAddress((void**)&xh,  g_xh);
    cudaGetSymbolAddress((void**)&Wqh, g_Wqh);
    cudaGetSymbolAddress((void**)&Wkh, g_Wkh);
    cudaGetSymbolAddress((void**)&Wvh, g_Wvh);
    cudaGetSymbolAddress((void**)&Woh, g_Woh);

    // Pre-convert inputs to fp16
    f32_to_f16<<<MROWS * DIM / 8 / 256, 256>>>(x, xh, MROWS * DIM);
    f32_to_f16<<<DIM * DIM / 8 / 256, 256>>>(Wq, Wqh, DIM * DIM);
    f32_to_f16<<<DIM * DIM / 8 / 256, 256>>>(Wk, Wkh, DIM * DIM);
    f32_to_f16<<<DIM * DIM / 8 / 256, 256>>>(Wv, Wvh, DIM * DIM);
    f32_to_f16<<<DIM * DIM / 8 / 256, 256>>>(Wo, Woh, DIM * DIM);

    // Fused Q/K/V projections (fp16 in, fp32 out)
    const dim3 g3(DIM / 128, MROWS / 128, 3);
    gemm3h_nt_bias<<<g3, 256>>>(xh, Wqh, Wkh, Wvh, bq, bk, bv, Q, K, V,
                                MROWS, DIM, DIM);

    // RoPE on Q and K
    const int rope_threads = BATCH * SEQ * NH * 32;
    const dim3 rgrid((rope_threads + 255) / 256, 2);
    rope_negsin_qk<<<rgrid, 256>>>(Q, K);

    // Flash attention -> fp16 Oh
    const dim3 agrid(SEQ / 64, NH, BATCH);
    flash_attn_f16<<<agrid, 128>>>(Q, K, V, Oh);

    // Output projection (fp16 in, fp32 out)
    const dim3 g1(DIM / 128, MROWS / 128, 1);
    gemm3h_nt_bias<<<g1, 256>>>(Oh, Woh, Woh, Woh, bo, bo, bo, out, out, out,
                                MROWS, DIM, DIM);
}

// round 16
// speedup vs baseline: 3.7162x; 1.0371x over previous
#include <cuda_runtime.h>
#include <cuda_fp16.h>
#include <math.h>
#include <stdint.h>

// Problem constants
#define BATCH 4
#define SEQ   1024
#define DIM   1024
#define NH    16
#define DH    64
#define MROWS (BATCH * SEQ)   // 4096

// Scratch (allocation-free rule: __device__ globals)
__device__ float  g_Q[MROWS * DIM];      // fp32 Q (pre-rope)
__device__ float  g_K[MROWS * DIM];      // fp32 K (pre-rope)
__device__ __half g_Qh[MROWS * DIM];     // fp16 Q (post-rope, pre-scaled)
__device__ __half g_Kh[MROWS * DIM];     // fp16 K (post-rope)
__device__ __half g_Vh[MROWS * DIM];     // fp16 V
__device__ __half g_Oh[MROWS * DIM];
__device__ __half g_xh[MROWS * DIM];
__device__ __half g_Wqh[DIM * DIM];
__device__ __half g_Wkh[DIM * DIM];
__device__ __half g_Wvh[DIM * DIM];
__device__ __half g_Woh[DIM * DIM];

// ----------------------------------------------------------------------------
// fp32 -> fp16 conversion
// ----------------------------------------------------------------------------
__global__ void f32_to_f16(const float* __restrict__ src, __half* __restrict__ dst, int n)
{
    const int i = (blockIdx.x * blockDim.x + threadIdx.x) * 8;
    if (i >= n) return;
    const float4 v0 = *(const float4*)(src + i);
    const float4 v1 = *(const float4*)(src + i + 4);
    uint4 h;
    ((__half2*)&h)[0] = __floats2half2_rn(v0.x, v0.y);
    ((__half2*)&h)[1] = __floats2half2_rn(v0.z, v0.w);
    ((__half2*)&h)[2] = __floats2half2_rn(v1.x, v1.y);
    ((__half2*)&h)[3] = __floats2half2_rn(v1.z, v1.w);
    *(uint4*)(dst + i) = h;
}

// ----------------------------------------------------------------------------
// FP16 NT GEMM with bias, cp.async 4-stage pipeline, fused over blockIdx.z.
// Outputs: z=0 -> C0 (f32), z=1 -> C1 (f32), z=2 -> C2h (fp16) if non-null,
// else C2 (f32). Tile 128x128x16, 8 warps, ldmatrix + mma.m16n8k16.
// ----------------------------------------------------------------------------
#define SAST 24                 // smem row stride in halves
#define STG_H (128 * SAST)
#define STG_B (STG_H * 2)

__global__ __launch_bounds__(256, 2) void gemm3h_nt_bias(
    const __half* __restrict__ A,
    const __half* __restrict__ W0, const __half* __restrict__ W1, const __half* __restrict__ W2,
    const float* __restrict__ b0, const float* __restrict__ b1, const float* __restrict__ b2,
    float* __restrict__ C0, float* __restrict__ C1,
    __half* __restrict__ C2h,
    int M, int N, int K)
{
    const int z = blockIdx.z;
    const __half* B   = (z == 0) ? W0 : (z == 1) ? W1 : W2;
    const float* bias = (z == 0) ? b0 : (z == 1) ? b1 : b2;

    __shared__ __align__(16) __half As[4][STG_H];
    __shared__ __align__(16) __half Bs[4][STG_H];

    const int bm   = blockIdx.y * 128;
    const int bn   = blockIdx.x * 128;
    const int t    = threadIdx.x;
    const int warp = t >> 5;
    const int lane = t & 31;
    const int wm2  = warp & 1;
    const int wn2  = warp >> 1;

    const int lrow = t >> 1;
    const int lk   = (t & 1) * 8;
    const __half* Ap = A + (size_t)(bm + lrow) * K + lk;
    const __half* Bp = B + (size_t)(bn + lrow) * K + lk;

    uint32_t as_base, bs_base;
    asm("{ .reg .u64 tmp; cvta.to.shared.u64 tmp, %1; cvt.u32.u64 %0, tmp; }"
        : "=r"(as_base) : "l"(&As[0][0]));
    asm("{ .reg .u64 tmp; cvta.to.shared.u64 tmp, %1; cvt.u32.u64 %0, tmp; }"
        : "=r"(bs_base) : "l"(&Bs[0][0]));
    const uint32_t a_st = as_base + 2 * (lrow * SAST + lk);
    const uint32_t b_st = bs_base + 2 * (lrow * SAST + lk);

    const int sub = lane >> 3;
    const int lr  = lane & 7;
    uint32_t a_addr[4], b_addr[2];
#pragma unroll
    for (int mt = 0; mt < 4; mt++) {
        const int row = wm2 * 64 + mt * 16 + (sub & 1) * 8 + lr;
        const int col = (sub >> 1) * 8;
        a_addr[mt] = as_base + 2 * (row * SAST + col);
    }
#pragma unroll
    for (int g = 0; g < 2; g++) {
        const int row = wn2 * 32 + g * 16 + (sub >> 1) * 8 + lr;
        const int col = (sub & 1) * 8;
        b_addr[g] = bs_base + 2 * (row * SAST + col);
    }

    float acc[4][4][4];
#pragma unroll
    for (int mt = 0; mt < 4; mt++)
#pragma unroll
        for (int nt = 0; nt < 4; nt++)
#pragma unroll
            for (int c = 0; c < 4; c++) acc[mt][nt][c] = 0.0f;

    const int NITER = K / 16;   // 64

#pragma unroll
    for (int s = 0; s < 3; s++) {
        asm volatile("cp.async.ca.shared.global [%0], [%1], 16;"
                     :: "r"(a_st + s * STG_B), "l"(Ap + s * 16));
        asm volatile("cp.async.ca.shared.global [%0], [%1], 16;"
                     :: "r"(b_st + s * STG_B), "l"(Bp + s * 16));
        asm volatile("cp.async.commit_group;");
    }

    for (int i = 0; i < NITER; i++) {
        asm volatile("cp.async.wait_group 2;");
        __syncthreads();

        if (i + 3 < NITER) {
            const int slot = (i + 3) & 3;
            asm volatile("cp.async.ca.shared.global [%0], [%1], 16;"
                         :: "r"(a_st + slot * STG_B), "l"(Ap + (i + 3) * 16));
            asm volatile("cp.async.ca.shared.global [%0], [%1], 16;"
                         :: "r"(b_st + slot * STG_B), "l"(Bp + (i + 3) * 16));
        }
        asm volatile("cp.async.commit_group;");

        const uint32_t soff = (uint32_t)((i & 3) * STG_B);

        uint32_t af[4][4];
#pragma unroll
        for (int mt = 0; mt < 4; mt++) {
            asm volatile(
                "ldmatrix.sync.aligned.m8n8.x4.shared.b16 {%0,%1,%2,%3}, [%4];"
                : "=r"(af[mt][0]), "=r"(af[mt][1]), "=r"(af[mt][2]), "=r"(af[mt][3])
                : "r"(a_addr[mt] + soff));
        }
        uint32_t bf[4][2];
#pragma unroll
        for (int g = 0; g < 2; g++) {
            asm volatile(
                "ldmatrix.sync.aligned.m8n8.x4.shared.b16 {%0,%1,%2,%3}, [%4];"
                : "=r"(bf[g * 2][0]), "=r"(bf[g * 2][1]),
                  "=r"(bf[g * 2 + 1][0]), "=r"(bf[g * 2 + 1][1])
                : "r"(b_addr[g] + soff));
        }

#pragma unroll
        for (int mt = 0; mt < 4; mt++)
#pragma unroll
            for (int nt = 0; nt < 4; nt++) {
                asm volatile(
                    "mma.sync.aligned.m16n8k16.row.col.f32.f16.f16.f32 "
                    "{%0,%1,%2,%3}, {%4,%5,%6,%7}, {%8,%9}, {%0,%1,%2,%3};"
                    : "+f"(acc[mt][nt][0]), "+f"(acc[mt][nt][1]),
                      "+f"(acc[mt][nt][2]), "+f"(acc[mt][nt][3])
                    : "r"(af[mt][0]), "r"(af[mt][1]), "r"(af[mt][2]), "r"(af[mt][3]),
                      "r"(bf[nt][0]), "r"(bf[nt][1]));
            }
    }

    const int gr  = lane >> 2;
    const int gcs = lane & 3;
    if (z == 2 && C2h) {
        // fp16 output (V path)
#pragma unroll
        for (int mt = 0; mt < 4; mt++) {
            const int m0 = bm + wm2 * 64 + mt * 16 + gr;
#pragma unroll
            for (int nt = 0; nt < 4; nt++) {
                const int n0 = bn + wn2 * 32 + nt * 8 + gcs * 2;
                const float bv0 = bias[n0];
                const float bv1 = bias[n0 + 1];
                __half2 h01 = __floats2half2_rn(acc[mt][nt][0] + bv0,
                                                acc[mt][nt][1] + bv1);
                __half2 h23 = __floats2half2_rn(acc[mt][nt][2] + bv0,
                                                acc[mt][nt][3] + bv1);
                *(uint32_t*)&C2h[(size_t)m0 * N + n0] = *(uint32_t*)&h01;
                *(uint32_t*)&C2h[(size_t)(m0 + 8) * N + n0] = *(uint32_t*)&h23;
            }
        }
    } else {
        float* C = (z == 0) ? C0 : C1;
#pragma unroll
        for (int mt = 0; mt < 4; mt++) {
            const int m0 = bm + wm2 * 64 + mt * 16 + gr;
#pragma unroll
            for (int nt = 0; nt < 4; nt++) {
                const int n0 = bn + wn2 * 32 + nt * 8 + gcs * 2;
                const float bv0 = bias[n0];
                const float bv1 = bias[n0 + 1];
                float2 v01;
                v01.x = acc[mt][nt][0] + bv0;
                v01.y = acc[mt][nt][1] + bv1;
                *(float2*)&C[(size_t)m0 * N + n0] = v01;
                float2 v23;
                v23.x = acc[mt][nt][2] + bv0;
                v23.y = acc[mt][nt][3] + bv1;
                *(float2*)&C[(size_t)(m0 + 8) * N + n0] = v23;
            }
        }
    }
}

// ----------------------------------------------------------------------------
// RoPE (-sin) fp32 -> fp16: reads fp32 Q/K, writes rotated fp16 Qh/Kh.
// Q path additionally folds the 1/sqrt(DH)=0.125 attention scale.
// ----------------------------------------------------------------------------
__global__ void rope_negsin_qk_h(const float* __restrict__ Q, const float* __restrict__ K,
                                 __half* __restrict__ Qh, __half* __restrict__ Kh)
{
    const int isK = blockIdx.y;
    const float* X = isK ? K : Q;
    __half* Y      = isK ? Kh : Qh;
    const float scale = isK ? 1.0f : 0.125f;

    const int idx = blockIdx.x * blockDim.x + threadIdx.x;
    const int total = BATCH * SEQ * NH * 32;
    if (idx >= total) return;
    const int j    = idx & 31;
    const int rest = idx >> 5;
    const int s    = (rest / NH) % SEQ;
    const size_t base = (size_t)rest * DH;

    const float inv_freq = expf(-((float)(2 * j) / (float)DH) * logf(10000.0f));
    const float ang = (float)s * inv_freq;
    float c, sn;
    sincosf(ang, &c, &sn);

    const float x1 = X[base + j];
    const float x2 = X[base + j + 32];
    Y[base + j]      = __float2half_rn((x1 * c + x2 * sn) * scale);   // reverse rotation
    Y[base + j + 32] = __float2half_rn((x2 * c - x1 * sn) * scale);
}

// ----------------------------------------------------------------------------
// FP16 tensor-core flash attention, all-fp16 inputs (Q pre-scaled by rope).
// Staging is raw uint4 copies (no conversion). Writes fp16 Oh.
// ----------------------------------------------------------------------------
#define FW 72   // flash smem row stride (halves)

__global__ __launch_bounds__(128) void flash_attn_f16(
    const __half* __restrict__ Q, const __half* __restrict__ K,
    const __half* __restrict__ V, __half* __restrict__ Oh)
{
    __shared__ __align__(16) __half Qs[64 * FW];
    __shared__ __align__(16) __half Ks[64 * FW];
    __shared__ __align__(16) __half Vs[64 * FW];

    const int qt = blockIdx.x;
    const int h  = blockIdx.y;
    const int b  = blockIdx.z;
    const int t  = threadIdx.x;
    const int warp = t >> 5;
    const int lane = t & 31;
    const int gr   = lane >> 2;
    const int gc   = lane & 3;
    const int sub  = lane >> 3;
    const int lr   = lane & 7;

    const int q0 = qt * 64;
    const int hcol = h * DH;
    const size_t seq_base = (size_t)b * SEQ * DIM + hcol;

    uint32_t qs_base, ks_base, vs_base;
    asm("{ .reg .u64 tmp; cvta.to.shared.u64 tmp, %1; cvt.u32.u64 %0, tmp; }"
        : "=r"(qs_base) : "l"(Qs));
    asm("{ .reg .u64 tmp; cvta.to.shared.u64 tmp, %1; cvt.u32.u64 %0, tmp; }"
        : "=r"(ks_base) : "l"(Ks));
    asm("{ .reg .u64 tmp; cvta.to.shared.u64 tmp, %1; cvt.u32.u64 %0, tmp; }"
        : "=r"(vs_base) : "l"(Vs));

    // Stage Q tile (raw fp16 copy)
    for (int u = t; u < 64 * 8; u += 128) {
        const int row = u >> 3;
        const int c   = (u & 7) * 8;
        *(uint4*)&Qs[row * FW + c] =
            *(const uint4*)&Q[seq_base + (size_t)(q0 + row) * DIM + c];
    }
    __syncthreads();

    uint32_t qf[4][4];
#pragma unroll
    for (int kc = 0; kc < 4; kc++) {
        const int row = warp * 16 + (sub & 1) * 8 + lr;
        const int col = kc * 16 + (sub >> 1) * 8;
        const uint32_t addr = qs_base + 2 * (row * FW + col);
        asm volatile(
            "ldmatrix.sync.aligned.m8n8.x4.shared.b16 {%0,%1,%2,%3}, [%4];"
            : "=r"(qf[kc][0]), "=r"(qf[kc][1]), "=r"(qf[kc][2]), "=r"(qf[kc][3])
            : "r"(addr));
    }

    float m0 = -1e30f, m1 = -1e30f, l0 = 0.0f, l1 = 0.0f;
    float o[8][4];
#pragma unroll
    for (int nt = 0; nt < 8; nt++)
#pragma unroll
        for (int c = 0; c < 4; c++) o[nt][c] = 0.0f;

    for (int kt = 0; kt < SEQ; kt += 64) {
        __syncthreads();
        for (int u = t; u < 64 * 8; u += 128) {
            const int row = u >> 3;
            const int c   = (u & 7) * 8;
            const size_t g = seq_base + (size_t)(kt + row) * DIM + c;
            *(uint4*)&Ks[row * FW + c] = *(const uint4*)&K[g];
            *(uint4*)&Vs[row * FW + c] = *(const uint4*)&V[g];
        }
        __syncthreads();

        float s[8][4];
#pragma unroll
        for (int nt = 0; nt < 8; nt++)
#pragma unroll
            for (int c = 0; c < 4; c++) s[nt][c] = 0.0f;

#pragma unroll
        for (int kc = 0; kc < 4; kc++) {
            uint32_t kf[8][2];
#pragma unroll
            for (int p = 0; p < 4; p++) {
                const int row = p * 16 + (sub >> 1) * 8 + lr;
                const int col = kc * 16 + (sub & 1) * 8;
                const uint32_t addr = ks_base + 2 * (row * FW + col);
                asm volatile(
                    "ldmatrix.sync.aligned.m8n8.x4.shared.b16 {%0,%1,%2,%3}, [%4];"
                    : "=r"(kf[p * 2][0]), "=r"(kf[p * 2][1]),
                      "=r"(kf[p * 2 + 1][0]), "=r"(kf[p * 2 + 1][1])
                    : "r"(addr));
            }
#pragma unroll
            for (int nt = 0; nt < 8; nt++) {
                asm volatile(
                    "mma.sync.aligned.m16n8k16.row.col.f32.f16.f16.f32 "
                    "{%0,%1,%2,%3}, {%4,%5,%6,%7}, {%8,%9}, {%0,%1,%2,%3};"
                    : "+f"(s[nt][0]), "+f"(s[nt][1]), "+f"(s[nt][2]), "+f"(s[nt][3])
                    : "r"(qf[kc][0]), "r"(qf[kc][1]), "r"(qf[kc][2]), "r"(qf[kc][3]),
                      "r"(kf[nt][0]), "r"(kf[nt][1]));
            }
        }

        float mx0 = -1e30f, mx1 = -1e30f;
#pragma unroll
        for (int nt = 0; nt < 8; nt++) {
            mx0 = fmaxf(mx0, fmaxf(s[nt][0], s[nt][1]));
            mx1 = fmaxf(mx1, fmaxf(s[nt][2], s[nt][3]));
        }
        mx0 = fmaxf(mx0, __shfl_xor_sync(0xffffffffu, mx0, 1));
        mx0 = fmaxf(mx0, __shfl_xor_sync(0xffffffffu, mx0, 2));
        mx1 = fmaxf(mx1, __shfl_xor_sync(0xffffffffu, mx1, 1));
        mx1 = fmaxf(mx1, __shfl_xor_sync(0xffffffffu, mx1, 2));

        const float nm0 = fmaxf(m0, mx0);
        const float nm1 = fmaxf(m1, mx1);
        const float corr0 = __expf(m0 - nm0);
        const float corr1 = __expf(m1 - nm1);
        m0 = nm0;
        m1 = nm1;

        float ps0 = 0.0f, ps1 = 0.0f;
#pragma unroll
        for (int nt = 0; nt < 8; nt++) {
            s[nt][0] = __expf(s[nt][0] - nm0);
            s[nt][1] = __expf(s[nt][1] - nm0);
            s[nt][2] = __expf(s[nt][2] - nm1);
            s[nt][3] = __expf(s[nt][3] - nm1);
            ps0 += s[nt][0] + s[nt][1];
            ps1 += s[nt][2] + s[nt][3];
        }
        ps0 += __shfl_xor_sync(0xffffffffu, ps0, 1);
        ps0 += __shfl_xor_sync(0xffffffffu, ps0, 2);
        ps1 += __shfl_xor_sync(0xffffffffu, ps1, 1);
        ps1 += __shfl_xor_sync(0xffffffffu, ps1, 2);
        l0 = l0 * corr0 + ps0;
        l1 = l1 * corr1 + ps1;

#pragma unroll
        for (int nt = 0; nt < 8; nt++) {
            o[nt][0] *= corr0;
            o[nt][1] *= corr0;
            o[nt][2] *= corr1;
            o[nt][3] *= corr1;
        }

#pragma unroll
        for (int kc = 0; kc < 4; kc++) {
            uint32_t pa[4];
            {
                __half2 h0 = __floats2half2_rn(s[2 * kc][0], s[2 * kc][1]);
                __half2 h1 = __floats2half2_rn(s[2 * kc][2], s[2 * kc][3]);
                __half2 h2 = __floats2half2_rn(s[2 * kc + 1][0], s[2 * kc + 1][1]);
                __half2 h3 = __floats2half2_rn(s[2 * kc + 1][2], s[2 * kc + 1][3]);
                pa[0] = *(uint32_t*)&h0;
                pa[1] = *(uint32_t*)&h1;
                pa[2] = *(uint32_t*)&h2;
                pa[3] = *(uint32_t*)&h3;
            }
            uint32_t vb[8][2];
#pragma unroll
            for (int pd = 0; pd < 4; pd++) {
                const int row = kc * 16 + (sub & 1) * 8 + lr;
                const int col = pd * 16 + (sub >> 1) * 8;
                const uint32_t addr = vs_base + 2 * (row * FW + col);
                asm volatile(
                    "ldmatrix.sync.aligned.m8n8.x4.trans.shared.b16 {%0,%1,%2,%3}, [%4];"
                    : "=r"(vb[pd * 2][0]), "=r"(vb[pd * 2][1]),
                      "=r"(vb[pd * 2 + 1][0]), "=r"(vb[pd * 2 + 1][1])
                    : "r"(addr));
            }
#pragma unroll
            for (int nt = 0; nt < 8; nt++) {
                asm volatile(
                    "mma.sync.aligned.m16n8k16.row.col.f32.f16.f16.f32 "
                    "{%0,%1,%2,%3}, {%4,%5,%6,%7}, {%8,%9}, {%0,%1,%2,%3};"
                    : "+f"(o[nt][0]), "+f"(o[nt][1]), "+f"(o[nt][2]), "+f"(o[nt][3])
                    : "r"(pa[0]), "r"(pa[1]), "r"(pa[2]), "r"(pa[3]),
                      "r"(vb[nt][0]), "r"(vb[nt][1]));
            }
        }
    }

    const float inv0 = 1.0f / l0;
    const float inv1 = 1.0f / l1;
    const size_t orow0 = seq_base + (size_t)(q0 + warp * 16 + gr) * DIM;
    const size_t orow1 = orow0 + (size_t)8 * DIM;
#pragma unroll
    for (int nt = 0; nt < 8; nt++) {
        const int n0 = nt * 8 + gc * 2;
        __half2 w0 = __floats2half2_rn(o[nt][0] * inv0, o[nt][1] * inv0);
        __half2 w1 = __floats2half2_rn(o[nt][2] * inv1, o[nt][3] * inv1);
        *(uint32_t*)&Oh[orow0 + n0] = *(uint32_t*)&w0;
        *(uint32_t*)&Oh[orow1 + n0] = *(uint32_t*)&w1;
    }
}

// ----------------------------------------------------------------------------
// Launch — strict dict-order input mapping: x, Wq, bq, Wk, bk, Wv, bv, Wo, bo
// ----------------------------------------------------------------------------
extern "C" void kernel_launch(void* const* d_in, const int* in_sizes, int n_in,
                              void* d_out, int out_size)
{
    (void)in_sizes; (void)n_in; (void)out_size;
    const float* x  = (const float*)d_in[0];
    const float* Wq = (const float*)d_in[1];
    const float* bq = (const float*)d_in[2];
    const float* Wk = (const float*)d_in[3];
    const float* bk = (const float*)d_in[4];
    const float* Wv = (const float*)d_in[5];
    const float* bv = (const float*)d_in[6];
    const float* Wo = (const float*)d_in[7];
    const float* bo = (const float*)d_in[8];
    float* out = (float*)d_out;

    float *Q, *K;
    __half *Qh, *Kh, *Vh, *Oh, *xh, *Wqh, *Wkh, *Wvh, *Woh;
    cudaGetSymbolAddress((void**)&Q,   g_Q);
    cudaGetSymbolAddress((void**)&K,   g_K);
    cudaGetSymbolAddress((void**)&Qh,  g_Qh);
    cudaGetSymbolAddress((void**)&Kh,  g_Kh);
    cudaGetSymbolAddress((void**)&Vh,  g_Vh);
    cudaGetSymbolAddress((void**)&Oh,  g_Oh);
    cudaGetSymbolAddress((void**)&xh,  g_xh);
    cudaGetSymbolAddress((void**)&Wqh, g_Wqh);
    cudaGetSymbolAddress((void**)&Wkh, g_Wkh);
    cudaGetSymbolAddress((void**)&Wvh, g_Wvh);
    cudaGetSymbolAddress((void**)&Woh, g_Woh);

    // Pre-convert inputs to fp16
    f32_to_f16<<<MROWS * DIM / 8 / 256, 256>>>(x, xh, MROWS * DIM);
    f32_to_f16<<<DIM * DIM / 8 / 256, 256>>>(Wq, Wqh, DIM * DIM);
    f32_to_f16<<<DIM * DIM / 8 / 256, 256>>>(Wk, Wkh, DIM * DIM);
    f32_to_f16<<<DIM * DIM / 8 / 256, 256>>>(Wv, Wvh, DIM * DIM);
    f32_to_f16<<<DIM * DIM / 8 / 256, 256>>>(Wo, Woh, DIM * DIM);

    // Fused Q/K/V projections: Q,K fp32; V fp16 direct
    const dim3 g3(DIM / 128, MROWS / 128, 3);
    gemm3h_nt_bias<<<g3, 256>>>(xh, Wqh, Wkh, Wvh, bq, bk, bv, Q, K, Vh,
                                MROWS, DIM, DIM);

    // RoPE fp32 -> fp16 (Q scaled by 1/8)
    const int rope_threads = BATCH * SEQ * NH * 32;
    const dim3 rgrid((rope_threads + 255) / 256, 2);
    rope_negsin_qk_h<<<rgrid, 256>>>(Q, K, Qh, Kh);

    // Flash attention (all fp16) -> fp16 Oh
    const dim3 agrid(SEQ / 64, NH, BATCH);
    flash_attn_f16<<<agrid, 128>>>(Qh, Kh, Vh, Oh);

    // Output projection (fp16 in, fp32 out; z=0 path)
    const dim3 g1(DIM / 128, MROWS / 128, 1);
    gemm3h_nt_bias<<<g1, 256>>>(Oh, Woh, Woh, Woh, bo, bo, bo, out, out,
                                (half*)0, MROWS, DIM, DIM);
}

// round 17
// speedup vs baseline: 3.8882x; 1.0463x over previous
#include <cuda_runtime.h>
#include <cuda_fp16.h>
#include <math.h>
#include <stdint.h>

// Problem constants
#define BATCH 4
#define SEQ   1024
#define DIM   1024
#define NH    16
#define DH    64
#define MROWS (BATCH * SEQ)   // 4096

// Scratch (allocation-free rule: __device__ globals)
__device__ float  g_Q[MROWS * DIM];      // fp32 Q (pre-rope)
__device__ float  g_K[MROWS * DIM];      // fp32 K (pre-rope)
__device__ __half g_Qh[MROWS * DIM];     // fp16 Q (post-rope, pre-scaled)
__device__ __half g_Kh[MROWS * DIM];     // fp16 K (post-rope)
__device__ __half g_Vh[MROWS * DIM];     // fp16 V
__device__ __half g_Oh[MROWS * DIM];
__device__ __half g_xh[MROWS * DIM];
__device__ __half g_Wqh[DIM * DIM];
__device__ __half g_Wkh[DIM * DIM];
__device__ __half g_Wvh[DIM * DIM];
__device__ __half g_Woh[DIM * DIM];

// ----------------------------------------------------------------------------
// Fused fp32 -> fp16 conversion for x + 4 weights in ONE launch.
// Layout: [0, 4M) -> x ; [4M + w*1M, ...) -> weight w (q,k,v,o).
// ----------------------------------------------------------------------------
#define XN (MROWS * DIM)          // 4194304
#define WN (DIM * DIM)            // 1048576
__global__ void convert_all(
    const float* __restrict__ x,
    const float* __restrict__ Wq, const float* __restrict__ Wk,
    const float* __restrict__ Wv, const float* __restrict__ Wo,
    __half* __restrict__ xh,
    __half* __restrict__ Wqh, __half* __restrict__ Wkh,
    __half* __restrict__ Wvh, __half* __restrict__ Woh)
{
    const long long i = (long long)(blockIdx.x * blockDim.x + threadIdx.x) * 8;
    const float* src;
    __half* dst;
    long long off;
    if (i < XN) {
        src = x; dst = xh; off = i;
    } else {
        const int w = (int)((i - XN) >> 20);        // /1M
        off = (i - XN) & (WN - 1);
        src = (w == 0) ? Wq : (w == 1) ? Wk : (w == 2) ? Wv : Wo;
        dst = (w == 0) ? Wqh : (w == 1) ? Wkh : (w == 2) ? Wvh : Woh;
    }
    const float4 v0 = *(const float4*)(src + off);
    const float4 v1 = *(const float4*)(src + off + 4);
    uint4 h;
    ((__half2*)&h)[0] = __floats2half2_rn(v0.x, v0.y);
    ((__half2*)&h)[1] = __floats2half2_rn(v0.z, v0.w);
    ((__half2*)&h)[2] = __floats2half2_rn(v1.x, v1.y);
    ((__half2*)&h)[3] = __floats2half2_rn(v1.z, v1.w);
    *(uint4*)(dst + off) = h;
}

// ----------------------------------------------------------------------------
// FP16 NT GEMM with bias, K-tile 32, cp.async 3-stage ring (dynamic smem),
// fused over blockIdx.z. Outputs: z<2 -> fp32 C0/C1; z=2 -> fp16 C2h.
// Tile 128x128x32, 8 warps (warp 64m x 32n), ldmatrix + mma.m16n8k16.
// Smem rows padded to 80B (40 halves): ldmatrix phases conflict-free
// (r*80 mod 128 all distinct for r in [0,8)).
// ----------------------------------------------------------------------------
#define SAST2 40                     // row stride in halves (80B)
#define STG2_H (128 * SAST2)         // 5120 halves per stage per operand
#define STG2_B (STG2_H * 2)          // 10240 bytes
#define G2_STAGES 3
#define G2_SMEM (G2_STAGES * 2 * STG2_B)   // 61440

__global__ __launch_bounds__(256, 2) void gemm3h_nt_bias(
    const __half* __restrict__ A,
    const __half* __restrict__ W0, const __half* __restrict__ W1, const __half* __restrict__ W2,
    const float* __restrict__ b0, const float* __restrict__ b1, const float* __restrict__ b2,
    float* __restrict__ C0, float* __restrict__ C1,
    __half* __restrict__ C2h,
    int M, int N, int K)
{
    extern __shared__ __align__(16) char dsm[];

    const int z = blockIdx.z;
    const __half* B   = (z == 0) ? W0 : (z == 1) ? W1 : W2;
    const float* bias = (z == 0) ? b0 : (z == 1) ? b1 : b2;

    const int bm   = blockIdx.y * 128;
    const int bn   = blockIdx.x * 128;
    const int t    = threadIdx.x;
    const int warp = t >> 5;
    const int lane = t & 31;
    const int wm2  = warp & 1;
    const int wn2  = warp >> 1;

    uint32_t as_base, bs_base;
    asm("{ .reg .u64 tmp; cvta.to.shared.u64 tmp, %1; cvt.u32.u64 %0, tmp; }"
        : "=r"(as_base) : "l"(dsm));
    bs_base = as_base + G2_STAGES * STG2_B;

    // Loader: 2 copy-slots per thread per operand per chunk.
    // u = t*2+j: row = u>>2 (0..127), 16B seg = u&3.
    uint32_t a_st[2], b_st[2];
    size_t aoff[2], boff[2];
#pragma unroll
    for (int j = 0; j < 2; j++) {
        const int u = t * 2 + j;
        const int row = u >> 2;
        const int seg = u & 3;
        a_st[j] = as_base + row * 80 + seg * 16;
        b_st[j] = bs_base + row * 80 + seg * 16;
        aoff[j] = (size_t)(bm + row) * K + seg * 8;
        boff[j] = (size_t)(bn + row) * K + seg * 8;
    }

    // ldmatrix addresses (stage 0): [mt][kc] for A, [g][kc] for B
    const int sub = lane >> 3;
    const int lr  = lane & 7;
    uint32_t a_addr[4][2], b_addr[2][2];
#pragma unroll
    for (int mt = 0; mt < 4; mt++) {
        const int row = wm2 * 64 + mt * 16 + (sub & 1) * 8 + lr;
#pragma unroll
        for (int kc = 0; kc < 2; kc++) {
            const int col = kc * 16 + (sub >> 1) * 8;
            a_addr[mt][kc] = as_base + row * 80 + col * 2;
        }
    }
#pragma unroll
    for (int g = 0; g < 2; g++) {
        const int row = wn2 * 32 + g * 16 + (sub >> 1) * 8 + lr;
#pragma unroll
        for (int kc = 0; kc < 2; kc++) {
            const int col = kc * 16 + (sub & 1) * 8;
            b_addr[g][kc] = bs_base + row * 80 + col * 2;
        }
    }

    float acc[4][4][4];
#pragma unroll
    for (int mt = 0; mt < 4; mt++)
#pragma unroll
        for (int nt = 0; nt < 4; nt++)
#pragma unroll
            for (int c = 0; c < 4; c++) acc[mt][nt][c] = 0.0f;

    const int NITER = K / 32;   // 32

    // Prologue: chunks 0,1 into stages 0,1
#pragma unroll
    for (int c = 0; c < 2; c++) {
#pragma unroll
        for (int j = 0; j < 2; j++) {
            asm volatile("cp.async.ca.shared.global [%0], [%1], 16;"
                         :: "r"(a_st[j] + c * STG2_B), "l"(A + aoff[j] + c * 32));
            asm volatile("cp.async.ca.shared.global [%0], [%1], 16;"
                         :: "r"(b_st[j] + c * STG2_B), "l"(B + boff[j] + c * 32));
        }
        asm volatile("cp.async.commit_group;");
    }

    int slot_c = 2;                // stage slot of chunk i+2 (cycles 2,0,1,...)
    int slot_i = 0;                // stage slot of chunk i
    for (int i = 0; i < NITER; i++) {
        asm volatile("cp.async.wait_group 1;");
        __syncthreads();

        if (i + 2 < NITER) {
#pragma unroll
            for (int j = 0; j < 2; j++) {
                asm volatile("cp.async.ca.shared.global [%0], [%1], 16;"
                             :: "r"(a_st[j] + slot_c * STG2_B), "l"(A + aoff[j] + (i + 2) * 32));
                asm volatile("cp.async.ca.shared.global [%0], [%1], 16;"
                             :: "r"(b_st[j] + slot_c * STG2_B), "l"(B + boff[j] + (i + 2) * 32));
            }
        }
        asm volatile("cp.async.commit_group;");

        const uint32_t soff = (uint32_t)(slot_i * STG2_B);

#pragma unroll
        for (int kc = 0; kc < 2; kc++) {
            uint32_t af[4][4];
#pragma unroll
            for (int mt = 0; mt < 4; mt++) {
                asm volatile(
                    "ldmatrix.sync.aligned.m8n8.x4.shared.b16 {%0,%1,%2,%3}, [%4];"
                    : "=r"(af[mt][0]), "=r"(af[mt][1]), "=r"(af[mt][2]), "=r"(af[mt][3])
                    : "r"(a_addr[mt][kc] + soff));
            }
            uint32_t bf[4][2];
#pragma unroll
            for (int g = 0; g < 2; g++) {
                asm volatile(
                    "ldmatrix.sync.aligned.m8n8.x4.shared.b16 {%0,%1,%2,%3}, [%4];"
                    : "=r"(bf[g * 2][0]), "=r"(bf[g * 2][1]),
                      "=r"(bf[g * 2 + 1][0]), "=r"(bf[g * 2 + 1][1])
                    : "r"(b_addr[g][kc] + soff));
            }
#pragma unroll
            for (int mt = 0; mt < 4; mt++)
#pragma unroll
                for (int nt = 0; nt < 4; nt++) {
                    asm volatile(
                        "mma.sync.aligned.m16n8k16.row.col.f32.f16.f16.f32 "
                        "{%0,%1,%2,%3}, {%4,%5,%6,%7}, {%8,%9}, {%0,%1,%2,%3};"
                        : "+f"(acc[mt][nt][0]), "+f"(acc[mt][nt][1]),
                          "+f"(acc[mt][nt][2]), "+f"(acc[mt][nt][3])
                        : "r"(af[mt][0]), "r"(af[mt][1]), "r"(af[mt][2]), "r"(af[mt][3]),
                          "r"(bf[nt][0]), "r"(bf[nt][1]));
                }
        }

        slot_i = (slot_i == 2) ? 0 : slot_i + 1;
        slot_c = (slot_c == 2) ? 0 : slot_c + 1;
    }

    const int gr  = lane >> 2;
    const int gcs = lane & 3;
    if (z == 2 && C2h) {
#pragma unroll
        for (int mt = 0; mt < 4; mt++) {
            const int m0 = bm + wm2 * 64 + mt * 16 + gr;
#pragma unroll
            for (int nt = 0; nt < 4; nt++) {
                const int n0 = bn + wn2 * 32 + nt * 8 + gcs * 2;
                const float bv0 = bias[n0];
                const float bv1 = bias[n0 + 1];
                __half2 h01 = __floats2half2_rn(acc[mt][nt][0] + bv0,
                                                acc[mt][nt][1] + bv1);
                __half2 h23 = __floats2half2_rn(acc[mt][nt][2] + bv0,
                                                acc[mt][nt][3] + bv1);
                *(uint32_t*)&C2h[(size_t)m0 * N + n0] = *(uint32_t*)&h01;
                *(uint32_t*)&C2h[(size_t)(m0 + 8) * N + n0] = *(uint32_t*)&h23;
            }
        }
    } else {
        float* C = (z == 0) ? C0 : C1;
#pragma unroll
        for (int mt = 0; mt < 4; mt++) {
            const int m0 = bm + wm2 * 64 + mt * 16 + gr;
#pragma unroll
            for (int nt = 0; nt < 4; nt++) {
                const int n0 = bn + wn2 * 32 + nt * 8 + gcs * 2;
                const float bv0 = bias[n0];
                const float bv1 = bias[n0 + 1];
                float2 v01;
                v01.x = acc[mt][nt][0] + bv0;
                v01.y = acc[mt][nt][1] + bv1;
                *(float2*)&C[(size_t)m0 * N + n0] = v01;
                float2 v23;
                v23.x = acc[mt][nt][2] + bv0;
                v23.y = acc[mt][nt][3] + bv1;
                *(float2*)&C[(size_t)(m0 + 8) * N + n0] = v23;
            }
        }
    }
}

// ----------------------------------------------------------------------------
// RoPE (-sin) fp32 -> fp16; Q path folds the 1/8 attention scale.
// ----------------------------------------------------------------------------
__global__ void rope_negsin_qk_h(const float* __restrict__ Q, const float* __restrict__ K,
                                 __half* __restrict__ Qh, __half* __restrict__ Kh)
{
    const int isK = blockIdx.y;
    const float* X = isK ? K : Q;
    __half* Y      = isK ? Kh : Qh;
    const float scale = isK ? 1.0f : 0.125f;

    const int idx = blockIdx.x * blockDim.x + threadIdx.x;
    const int total = BATCH * SEQ * NH * 32;
    if (idx >= total) return;
    const int j    = idx & 31;
    const int rest = idx >> 5;
    const int s    = (rest / NH) % SEQ;
    const size_t base = (size_t)rest * DH;

    const float inv_freq = expf(-((float)(2 * j) / (float)DH) * logf(10000.0f));
    const float ang = (float)s * inv_freq;
    float c, sn;
    sincosf(ang, &c, &sn);

    const float x1 = X[base + j];
    const float x2 = X[base + j + 32];
    Y[base + j]      = __float2half_rn((x1 * c + x2 * sn) * scale);   // reverse rotation
    Y[base + j + 32] = __float2half_rn((x2 * c - x1 * sn) * scale);
}

// ----------------------------------------------------------------------------
// FP16 tensor-core flash attention, all-fp16 inputs. Unchanged from R16.
// ----------------------------------------------------------------------------
#define FW 72   // flash smem row stride (halves)

__global__ __launch_bounds__(128) void flash_attn_f16(
    const __half* __restrict__ Q, const __half* __restrict__ K,
    const __half* __restrict__ V, __half* __restrict__ Oh)
{
    __shared__ __align__(16) __half Qs[64 * FW];
    __shared__ __align__(16) __half Ks[64 * FW];
    __shared__ __align__(16) __half Vs[64 * FW];

    const int qt = blockIdx.x;
    const int h  = blockIdx.y;
    const int b  = blockIdx.z;
    const int t  = threadIdx.x;
    const int warp = t >> 5;
    const int lane = t & 31;
    const int gr   = lane >> 2;
    const int gc   = lane & 3;
    const int sub  = lane >> 3;
    const int lr   = lane & 7;

    const int q0 = qt * 64;
    const int hcol = h * DH;
    const size_t seq_base = (size_t)b * SEQ * DIM + hcol;

    uint32_t qs_base, ks_base, vs_base;
    asm("{ .reg .u64 tmp; cvta.to.shared.u64 tmp, %1; cvt.u32.u64 %0, tmp; }"
        : "=r"(qs_base) : "l"(Qs));
    asm("{ .reg .u64 tmp; cvta.to.shared.u64 tmp, %1; cvt.u32.u64 %0, tmp; }"
        : "=r"(ks_base) : "l"(Ks));
    asm("{ .reg .u64 tmp; cvta.to.shared.u64 tmp, %1; cvt.u32.u64 %0, tmp; }"
        : "=r"(vs_base) : "l"(Vs));

    for (int u = t; u < 64 * 8; u += 128) {
        const int row = u >> 3;
        const int c   = (u & 7) * 8;
        *(uint4*)&Qs[row * FW + c] =
            *(const uint4*)&Q[seq_base + (size_t)(q0 + row) * DIM + c];
    }
    __syncthreads();

    uint32_t qf[4][4];
#pragma unroll
    for (int kc = 0; kc < 4; kc++) {
        const int row = warp * 16 + (sub & 1) * 8 + lr;
        const int col = kc * 16 + (sub >> 1) * 8;
        const uint32_t addr = qs_base + 2 * (row * FW + col);
        asm volatile(
            "ldmatrix.sync.aligned.m8n8.x4.shared.b16 {%0,%1,%2,%3}, [%4];"
            : "=r"(qf[kc][0]), "=r"(qf[kc][1]), "=r"(qf[kc][2]), "=r"(qf[kc][3])
            : "r"(addr));
    }

    float m0 = -1e30f, m1 = -1e30f, l0 = 0.0f, l1 = 0.0f;
    float o[8][4];
#pragma unroll
    for (int nt = 0; nt < 8; nt++)
#pragma unroll
        for (int c = 0; c < 4; c++) o[nt][c] = 0.0f;

    for (int kt = 0; kt < SEQ; kt += 64) {
        __syncthreads();
        for (int u = t; u < 64 * 8; u += 128) {
            const int row = u >> 3;
            const int c   = (u & 7) * 8;
            const size_t g = seq_base + (size_t)(kt + row) * DIM + c;
            *(uint4*)&Ks[row * FW + c] = *(const uint4*)&K[g];
            *(uint4*)&Vs[row * FW + c] = *(const uint4*)&V[g];
        }
        __syncthreads();

        float s[8][4];
#pragma unroll
        for (int nt = 0; nt < 8; nt++)
#pragma unroll
            for (int c = 0; c < 4; c++) s[nt][c] = 0.0f;

#pragma unroll
        for (int kc = 0; kc < 4; kc++) {
            uint32_t kf[8][2];
#pragma unroll
            for (int p = 0; p < 4; p++) {
                const int row = p * 16 + (sub >> 1) * 8 + lr;
                const int col = kc * 16 + (sub & 1) * 8;
                const uint32_t addr = ks_base + 2 * (row * FW + col);
                asm volatile(
                    "ldmatrix.sync.aligned.m8n8.x4.shared.b16 {%0,%1,%2,%3}, [%4];"
                    : "=r"(kf[p * 2][0]), "=r"(kf[p * 2][1]),
                      "=r"(kf[p * 2 + 1][0]), "=r"(kf[p * 2 + 1][1])
                    : "r"(addr));
            }
#pragma unroll
            for (int nt = 0; nt < 8; nt++) {
                asm volatile(
                    "mma.sync.aligned.m16n8k16.row.col.f32.f16.f16.f32 "
                    "{%0,%1,%2,%3}, {%4,%5,%6,%7}, {%8,%9}, {%0,%1,%2,%3};"
                    : "+f"(s[nt][0]), "+f"(s[nt][1]), "+f"(s[nt][2]), "+f"(s[nt][3])
                    : "r"(qf[kc][0]), "r"(qf[kc][1]), "r"(qf[kc][2]), "r"(qf[kc][3]),
                      "r"(kf[nt][0]), "r"(kf[nt][1]));
            }
        }

        float mx0 = -1e30f, mx1 = -1e30f;
#pragma unroll
        for (int nt = 0; nt < 8; nt++) {
            mx0 = fmaxf(mx0, fmaxf(s[nt][0], s[nt][1]));
            mx1 = fmaxf(mx1, fmaxf(s[nt][2], s[nt][3]));
        }
        mx0 = fmaxf(mx0, __shfl_xor_sync(0xffffffffu, mx0, 1));
        mx0 = fmaxf(mx0, __shfl_xor_sync(0xffffffffu, mx0, 2));
        mx1 = fmaxf(mx1, __shfl_xor_sync(0xffffffffu, mx1, 1));
        mx1 = fmaxf(mx1, __shfl_xor_sync(0xffffffffu, mx1, 2));

        const float nm0 = fmaxf(m0, mx0);
        const float nm1 = fmaxf(m1, mx1);
        const float corr0 = __expf(m0 - nm0);
        const float corr1 = __expf(m1 - nm1);
        m0 = nm0;
        m1 = nm1;

        float ps0 = 0.0f, ps1 = 0.0f;
#pragma unroll
        for (int nt = 0; nt < 8; nt++) {
            s[nt][0] = __expf(s[nt][0] - nm0);
            s[nt][1] = __expf(s[nt][1] - nm0);
            s[nt][2] = __expf(s[nt][2] - nm1);
            s[nt][3] = __expf(s[nt][3] - nm1);
            ps0 += s[nt][0] + s[nt][1];
            ps1 += s[nt][2] + s[nt][3];
        }
        ps0 += __shfl_xor_sync(0xffffffffu, ps0, 1);
        ps0 += __shfl_xor_sync(0xffffffffu, ps0, 2);
        ps1 += __shfl_xor_sync(0xffffffffu, ps1, 1);
        ps1 += __shfl_xor_sync(0xffffffffu, ps1, 2);
        l0 = l0 * corr0 + ps0;
        l1 = l1 * corr1 + ps1;

#pragma unroll
        for (int nt = 0; nt < 8; nt++) {
            o[nt][0] *= corr0;
            o[nt][1] *= corr0;
            o[nt][2] *= corr1;
            o[nt][3] *= corr1;
        }

#pragma unroll
        for (int kc = 0; kc < 4; kc++) {
            uint32_t pa[4];
            {
                __half2 h0 = __floats2half2_rn(s[2 * kc][0], s[2 * kc][1]);
                __half2 h1 = __floats2half2_rn(s[2 * kc][2], s[2 * kc][3]);
                __half2 h2 = __floats2half2_rn(s[2 * kc + 1][0], s[2 * kc + 1][1]);
                __half2 h3 = __floats2half2_rn(s[2 * kc + 1][2], s[2 * kc + 1][3]);
                pa[0] = *(uint32_t*)&h0;
                pa[1] = *(uint32_t*)&h1;
                pa[2] = *(uint32_t*)&h2;
                pa[3] = *(uint32_t*)&h3;
            }
            uint32_t vb[8][2];
#pragma unroll
            for (int pd = 0; pd < 4; pd++) {
                const int row = kc * 16 + (sub & 1) * 8 + lr;
                const int col = pd * 16 + (sub >> 1) * 8;
                const uint32_t addr = vs_base + 2 * (row * FW + col);
                asm volatile(
                    "ldmatrix.sync.aligned.m8n8.x4.trans.shared.b16 {%0,%1,%2,%3}, [%4];"
                    : "=r"(vb[pd * 2][0]), "=r"(vb[pd * 2][1]),
                      "=r"(vb[pd * 2 + 1][0]), "=r"(vb[pd * 2 + 1][1])
                    : "r"(addr));
            }
#pragma unroll
            for (int nt = 0; nt < 8; nt++) {
                asm volatile(
                    "mma.sync.aligned.m16n8k16.row.col.f32.f16.f16.f32 "
                    "{%0,%1,%2,%3}, {%4,%5,%6,%7}, {%8,%9}, {%0,%1,%2,%3};"
                    : "+f"(o[nt][0]), "+f"(o[nt][1]), "+f"(o[nt][2]), "+f"(o[nt][3])
                    : "r"(pa[0]), "r"(pa[1]), "r"(pa[2]), "r"(pa[3]),
                      "r"(vb[nt][0]), "r"(vb[nt][1]));
            }
        }
    }

    const float inv0 = 1.0f / l0;
    const float inv1 = 1.0f / l1;
    const size_t orow0 = seq_base + (size_t)(q0 + warp * 16 + gr) * DIM;
    const size_t orow1 = orow0 + (size_t)8 * DIM;
#pragma unroll
    for (int nt = 0; nt < 8; nt++) {
        const int n0 = nt * 8 + gc * 2;
        __half2 w0 = __floats2half2_rn(o[nt][0] * inv0, o[nt][1] * inv0);
        __half2 w1 = __floats2half2_rn(o[nt][2] * inv1, o[nt][3] * inv1);
        *(uint32_t*)&Oh[orow0 + n0] = *(uint32_t*)&w0;
        *(uint32_t*)&Oh[orow1 + n0] = *(uint32_t*)&w1;
    }
}

// ----------------------------------------------------------------------------
// Launch — strict dict-order input mapping: x, Wq, bq, Wk, bk, Wv, bv, Wo, bo
// ----------------------------------------------------------------------------
extern "C" void kernel_launch(void* const* d_in, const int* in_sizes, int n_in,
                              void* d_out, int out_size)
{
    (void)in_sizes; (void)n_in; (void)out_size;
    const float* x  = (const float*)d_in[0];
    const float* Wq = (const float*)d_in[1];
    const float* bq = (const float*)d_in[2];
    const float* Wk = (const float*)d_in[3];
    const float* bk = (const float*)d_in[4];
    const float* Wv = (const float*)d_in[5];
    const float* bv = (const float*)d_in[6];
    const float* Wo = (const float*)d_in[7];
    const float* bo = (const float*)d_in[8];
    float* out = (float*)d_out;

    float *Q, *K;
    __half *Qh, *Kh, *Vh, *Oh, *xh, *Wqh, *Wkh, *Wvh, *Woh;
    cudaGetSymbolAddress((void**)&Q,   g_Q);
    cudaGetSymbolAddress((void**)&K,   g_K);
    cudaGetSymbolAddress((void**)&Qh,  g_Qh);
    cudaGetSymbolAddress((void**)&Kh,  g_Kh);
    cudaGetSymbolAddress((void**)&Vh,  g_Vh);
    cudaGetSymbolAddress((void**)&Oh,  g_Oh);
    cudaGetSymbolAddress((void**)&xh,  g_xh);
    cudaGetSymbolAddress((void**)&Wqh, g_Wqh);
    cudaGetSymbolAddress((void**)&Wkh, g_Wkh);
    cudaGetSymbolAddress((void**)&Wvh, g_Wvh);
    cudaGetSymbolAddress((void**)&Woh, g_Woh);

    cudaFuncSetAttribute(gemm3h_nt_bias, cudaFuncAttributeMaxDynamicSharedMemorySize,
                         G2_SMEM);

    // One fused convert launch (x + 4 weights = 8M elements)
    convert_all<<<(XN + 4 * WN) / 8 / 256, 256>>>(x, Wq, Wk, Wv, Wo,
                                                  xh, Wqh, Wkh, Wvh, Woh);

    // Fused Q/K/V projections: Q,K fp32; V fp16 direct
    const dim3 g3(DIM / 128, MROWS / 128, 3);
    gemm3h_nt_bias<<<g3, 256, G2_SMEM>>>(xh, Wqh, Wkh, Wvh, bq, bk, bv, Q, K, Vh,
                                         MROWS, DIM, DIM);

    // RoPE fp32 -> fp16 (Q scaled by 1/8)
    const int rope_threads = BATCH * SEQ * NH * 32;
    const dim3 rgrid((rope_threads + 255) / 256, 2);
    rope_negsin_qk_h<<<rgrid, 256>>>(Q, K, Qh, Kh);

    // Flash attention (all fp16) -> fp16 Oh
    const dim3 agrid(SEQ / 64, NH, BATCH);
    flash_attn_f16<<<agrid, 128>>>(Qh, Kh, Vh, Oh);

    // Output projection (fp16 in, fp32 out; z=0 path)
    const dim3 g1(DIM / 128, MROWS / 128, 1);
    gemm3h_nt_bias<<<g1, 256, G2_SMEM>>>(Oh, Woh, Woh, Woh, bo, bo, bo, out, out,
                                         (half*)0, MROWS, DIM, DIM);
}